// round 5
// baseline (speedup 1.0000x reference)
#include <cuda_runtime.h>
#include <cuda_bf16.h>
#include <cstdint>

// Problem constants
#define NNODES 50000
#define NEDGES 800000
#define INDIM  128
#define HID    256
#define NGRAPH 128
#define NCLS   16

// ---------------- device scratch ----------------
__device__ float          g_bufA[NNODES * HID];   // fp32 activations
__device__ __nv_bfloat16  g_bufH[NNODES * HID];   // bf16 h' (messages)
__device__ float g_dinv[NNODES];
__device__ int   g_indeg[NNODES];
__device__ int   g_row_ptr[NNODES + 1];
__device__ int   g_cursor[NNODES];
__device__ int   g_csr_src[NEDGES];
__device__ int   g_localscan[NNODES];
__device__ int   g_blocksum[64];
__device__ int   g_blockoff[64];
__device__ int   g_gstart[NGRAPH + 1];
__device__ float g_pool[NGRAPH * HID];
__device__ int   g_is64;

__device__ __forceinline__ int get_idx(const void* p, int i, int is64) {
    if (is64) return (int)((const long long*)p)[i];
    return ((const int*)p)[i];
}

__device__ __forceinline__ uint32_t f2tf32(float f) {
    uint32_t u;
    asm("cvt.rna.tf32.f32 %0, %1;" : "=r"(u) : "f"(f));
    return u;
}

// ---------------- dtype detection ----------------
__global__ void detect_dtype_kernel(const int* __restrict__ w, int nOddSamples) {
    __shared__ int found;
    if (threadIdx.x == 0) found = 0;
    __syncthreads();
    for (int i = threadIdx.x; i < nOddSamples; i += blockDim.x) {
        if (w[2 * i + 1] != 0) found = 1;
    }
    __syncthreads();
    if (threadIdx.x == 0) g_is64 = found ? 0 : 1;
}

// ---------------- preprocessing ----------------
__global__ void zero_int_kernel(int* p, int n) {
    int i = blockIdx.x * blockDim.x + threadIdx.x;
    if (i < n) p[i] = 0;
}

__global__ void hist_dst_kernel(const void* __restrict__ ei, int E, int* __restrict__ indeg) {
    int e = blockIdx.x * blockDim.x + threadIdx.x;
    if (e < E) {
        int d = get_idx(ei, E + e, g_is64);
        atomicAdd(&indeg[d], 1);
    }
}

// batch is sorted: gstart[g] = first index with batch[i] >= g
__global__ void gstart_binsearch_kernel(const void* __restrict__ batch, int n, int* __restrict__ gstart) {
    int g = threadIdx.x;
    if (g > NGRAPH) return;
    int is64 = g_is64;
    int lo = 0, hi = n;
    while (lo < hi) {
        int mid = (lo + hi) >> 1;
        if (get_idx(batch, mid, is64) < g) lo = mid + 1; else hi = mid;
    }
    gstart[g] = lo;
}

__global__ void scan_local_kernel(const int* __restrict__ counts, int* __restrict__ localscan, int n) {
    __shared__ int s[1024];
    int tid = threadIdx.x;
    int i = blockIdx.x * 1024 + tid;
    int v = (i < n) ? counts[i] : 0;
    s[tid] = v;
    __syncthreads();
    for (int off = 1; off < 1024; off <<= 1) {
        int t = (tid >= off) ? s[tid - off] : 0;
        __syncthreads();
        s[tid] += t;
        __syncthreads();
    }
    if (i < n) localscan[i] = s[tid];
    if (tid == 1023) g_blocksum[blockIdx.x] = s[1023];
}

__global__ void scan_blocksums_kernel(int nb) {
    __shared__ int s[64];
    int tid = threadIdx.x;
    int v = (tid < nb) ? g_blocksum[tid] : 0;
    s[tid] = v;
    __syncthreads();
    for (int off = 1; off < 64; off <<= 1) {
        int t = (tid >= off) ? s[tid - off] : 0;
        __syncthreads();
        s[tid] += t;
        __syncthreads();
    }
    g_blockoff[tid] = s[tid] - v;
}

__global__ void scan_finalize_kernel(const int* __restrict__ counts, const int* __restrict__ localscan,
                                     int* __restrict__ row_ptr, int* __restrict__ cursor,
                                     float* __restrict__ dinv, int n) {
    int i = blockIdx.x * blockDim.x + threadIdx.x;
    if (i < n) {
        int cnt = counts[i];
        int incl = localscan[i] + g_blockoff[i >> 10];
        row_ptr[i + 1] = incl;
        cursor[i] = incl - cnt;
        dinv[i] = rsqrtf((float)cnt + 1.0f);
        if (i == 0) row_ptr[0] = 0;
    }
}

__global__ void fill_csr_kernel(const void* __restrict__ ei, int E,
                                int* __restrict__ cursor, int* __restrict__ csr_src) {
    int e = blockIdx.x * blockDim.x + threadIdx.x;
    if (e < E) {
        int is64 = g_is64;
        int d = get_idx(ei, E + e, is64);
        int s = get_idx(ei, e, is64);
        int pos = atomicAdd(&cursor[d], 1);
        csr_src[pos] = s;
    }
}

// ---------------- TF32 tensor-core GEMM ----------------
// C[M,256] = A[M,K] @ B[K,256]; epilogue: +bias (fp32 out) OR *scale -> bf16 out
#define BM 128
#define BN 128
#define BK 16
#define AS_K 20
#define BS_N 136

__global__ __launch_bounds__(256, 2) void tf32gemm_kernel(
    const float* __restrict__ A, const float* __restrict__ B,
    float* __restrict__ C, __nv_bfloat16* __restrict__ Cbf,
    int M, int K, const float* __restrict__ bias, const float* __restrict__ scale) {
    __shared__ uint32_t As[BM * AS_K];
    __shared__ uint32_t Bs[BK * BS_N];

    const int tid = threadIdx.x;
    const int colBase = blockIdx.x * BN;
    const int rowBase = blockIdx.y * BM;

    const int wid = tid >> 5;
    const int lane = tid & 31;
    const int warpM = wid & 3;
    const int warpN = wid >> 2;
    const int g = lane >> 2;
    const int t4 = lane & 3;
    const int mB = warpM * 32;
    const int nB = warpN * 64;

    const int aRow0 = tid >> 2;
    const int aRow1 = 64 + (tid >> 2);
    const int aC = (tid & 3) * 4;
    const int bRow0 = tid >> 5;
    const int bRow1 = 8 + (tid >> 5);
    const int bCol = (tid & 31) * 4;

    int gr0 = rowBase + aRow0; gr0 = gr0 < M ? gr0 : M - 1;
    int gr1 = rowBase + aRow1; gr1 = gr1 < M ? gr1 : M - 1;
    const float* aPtr0 = A + (size_t)gr0 * K + aC;
    const float* aPtr1 = A + (size_t)gr1 * K + aC;
    const float* bPtr0 = B + (size_t)bRow0 * HID + colBase + bCol;
    const float* bPtr1 = B + (size_t)bRow1 * HID + colBase + bCol;

    float acc[2][8][4];
#pragma unroll
    for (int mt = 0; mt < 2; mt++)
#pragma unroll
        for (int nt = 0; nt < 8; nt++)
#pragma unroll
            for (int c = 0; c < 4; c++) acc[mt][nt][c] = 0.0f;

    const int nTiles = K / BK;

    float4 pa0 = *reinterpret_cast<const float4*>(aPtr0);
    float4 pa1 = *reinterpret_cast<const float4*>(aPtr1);
    float4 pb0 = *reinterpret_cast<const float4*>(bPtr0);
    float4 pb1 = *reinterpret_cast<const float4*>(bPtr1);

    for (int t = 0; t < nTiles; t++) {
        {
            uint4 ua0 = make_uint4(f2tf32(pa0.x), f2tf32(pa0.y), f2tf32(pa0.z), f2tf32(pa0.w));
            uint4 ua1 = make_uint4(f2tf32(pa1.x), f2tf32(pa1.y), f2tf32(pa1.z), f2tf32(pa1.w));
            uint4 ub0 = make_uint4(f2tf32(pb0.x), f2tf32(pb0.y), f2tf32(pb0.z), f2tf32(pb0.w));
            uint4 ub1 = make_uint4(f2tf32(pb1.x), f2tf32(pb1.y), f2tf32(pb1.z), f2tf32(pb1.w));
            *reinterpret_cast<uint4*>(&As[aRow0 * AS_K + aC]) = ua0;
            *reinterpret_cast<uint4*>(&As[aRow1 * AS_K + aC]) = ua1;
            *reinterpret_cast<uint4*>(&Bs[bRow0 * BS_N + bCol]) = ub0;
            *reinterpret_cast<uint4*>(&Bs[bRow1 * BS_N + bCol]) = ub1;
        }
        __syncthreads();

        if (t + 1 < nTiles) {
            int k0 = (t + 1) * BK;
            pa0 = *reinterpret_cast<const float4*>(aPtr0 + k0);
            pa1 = *reinterpret_cast<const float4*>(aPtr1 + k0);
            pb0 = *reinterpret_cast<const float4*>(bPtr0 + (size_t)k0 * HID);
            pb1 = *reinterpret_cast<const float4*>(bPtr1 + (size_t)k0 * HID);
        }

#pragma unroll
        for (int ks = 0; ks < BK; ks += 8) {
            uint32_t af[2][4];
#pragma unroll
            for (int mt = 0; mt < 2; mt++) {
                int m0 = mB + mt * 16 + g;
                af[mt][0] = As[m0 * AS_K + ks + t4];
                af[mt][1] = As[(m0 + 8) * AS_K + ks + t4];
                af[mt][2] = As[m0 * AS_K + ks + t4 + 4];
                af[mt][3] = As[(m0 + 8) * AS_K + ks + t4 + 4];
            }
            uint32_t bf[8][2];
#pragma unroll
            for (int nt = 0; nt < 8; nt++) {
                int n0 = nB + nt * 8 + g;
                bf[nt][0] = Bs[(ks + t4) * BS_N + n0];
                bf[nt][1] = Bs[(ks + t4 + 4) * BS_N + n0];
            }
#pragma unroll
            for (int mt = 0; mt < 2; mt++)
#pragma unroll
                for (int nt = 0; nt < 8; nt++) {
                    asm volatile(
                        "mma.sync.aligned.m16n8k8.row.col.f32.tf32.tf32.f32 "
                        "{%0,%1,%2,%3}, {%4,%5,%6,%7}, {%8,%9}, {%0,%1,%2,%3};"
                        : "+f"(acc[mt][nt][0]), "+f"(acc[mt][nt][1]),
                          "+f"(acc[mt][nt][2]), "+f"(acc[mt][nt][3])
                        : "r"(af[mt][0]), "r"(af[mt][1]), "r"(af[mt][2]), "r"(af[mt][3]),
                          "r"(bf[nt][0]), "r"(bf[nt][1]));
                }
        }
        __syncthreads();
    }

    // epilogue
#pragma unroll
    for (int mt = 0; mt < 2; mt++) {
        int r0 = rowBase + mB + mt * 16 + g;
        int r1 = r0 + 8;
        float s0 = 1.0f, s1 = 1.0f;
        if (scale) {
            if (r0 < M) s0 = scale[r0];
            if (r1 < M) s1 = scale[r1];
        }
#pragma unroll
        for (int nt = 0; nt < 8; nt++) {
            int c = colBase + nB + nt * 8 + t4 * 2;
            float bx = 0.f, by = 0.f;
            if (bias) { bx = bias[c]; by = bias[c + 1]; }
            float v0x = acc[mt][nt][0] * s0 + bx;
            float v0y = acc[mt][nt][1] * s0 + by;
            float v1x = acc[mt][nt][2] * s1 + bx;
            float v1y = acc[mt][nt][3] * s1 + by;
            if (Cbf) {
                if (r0 < M) {
                    __nv_bfloat162 p = __floats2bfloat162_rn(v0x, v0y);
                    *reinterpret_cast<__nv_bfloat162*>(&Cbf[(size_t)r0 * HID + c]) = p;
                }
                if (r1 < M) {
                    __nv_bfloat162 p = __floats2bfloat162_rn(v1x, v1y);
                    *reinterpret_cast<__nv_bfloat162*>(&Cbf[(size_t)r1 * HID + c]) = p;
                }
            } else {
                if (r0 < M) {
                    float2 v = make_float2(v0x, v0y);
                    *reinterpret_cast<float2*>(&C[(size_t)r0 * HID + c]) = v;
                }
                if (r1 < M) {
                    float2 v = make_float2(v1x, v1y);
                    *reinterpret_cast<float2*>(&C[(size_t)r1 * HID + c]) = v;
                }
            }
        }
    }
}

// ---------------- gather (bf16 in, fp32 out) ----------------
// out[d,:] = relu(dinv[d]*(sum_{src} hp[src,:] + hp[d,:]) + b[:])
__global__ void gather_kernel(const __nv_bfloat16* __restrict__ hp, float* __restrict__ out,
                              const int* __restrict__ row_ptr, const int* __restrict__ csr_src,
                              const float* __restrict__ dinv, const float* __restrict__ bias, int n) {
    int warp = (blockIdx.x * blockDim.x + threadIdx.x) >> 5;
    int lane = threadIdx.x & 31;
    if (warp >= n) return;
    int beg = row_ptr[warp];
    int end = row_ptr[warp + 1];

    float acc[8];
#pragma unroll
    for (int j = 0; j < 8; j++) acc[j] = 0.0f;

    // each lane handles 8 consecutive bf16 (16 bytes) at column lane*8
    const int colOff = lane * 8;

    for (int e = beg; e < end; e++) {
        int src = csr_src[e];
        uint4 u = __ldg(reinterpret_cast<const uint4*>(hp + (size_t)src * HID + colOff));
        const __nv_bfloat162* p = reinterpret_cast<const __nv_bfloat162*>(&u);
#pragma unroll
        for (int q = 0; q < 4; q++) {
            float2 f = __bfloat1622float2(p[q]);
            acc[2 * q] += f.x;
            acc[2 * q + 1] += f.y;
        }
    }
    // self contribution
    {
        uint4 u = *reinterpret_cast<const uint4*>(hp + (size_t)warp * HID + colOff);
        const __nv_bfloat162* p = reinterpret_cast<const __nv_bfloat162*>(&u);
#pragma unroll
        for (int q = 0; q < 4; q++) {
            float2 f = __bfloat1622float2(p[q]);
            acc[2 * q] += f.x;
            acc[2 * q + 1] += f.y;
        }
    }
    float dv = dinv[warp];
    float4 b0 = *reinterpret_cast<const float4*>(bias + colOff);
    float4 b1 = *reinterpret_cast<const float4*>(bias + colOff + 4);
    float4 o0, o1;
    o0.x = fmaxf(dv * acc[0] + b0.x, 0.f);
    o0.y = fmaxf(dv * acc[1] + b0.y, 0.f);
    o0.z = fmaxf(dv * acc[2] + b0.z, 0.f);
    o0.w = fmaxf(dv * acc[3] + b0.w, 0.f);
    o1.x = fmaxf(dv * acc[4] + b1.x, 0.f);
    o1.y = fmaxf(dv * acc[5] + b1.y, 0.f);
    o1.z = fmaxf(dv * acc[6] + b1.z, 0.f);
    o1.w = fmaxf(dv * acc[7] + b1.w, 0.f);

    float* outrow = out + (size_t)warp * HID + colOff;
    *reinterpret_cast<float4*>(outrow) = o0;
    *reinterpret_cast<float4*>(outrow + 4) = o1;
}

// ---------------- pooling ----------------
__global__ void pool_mean_kernel(const float* __restrict__ h, const int* __restrict__ gstart,
                                 float* __restrict__ pooled) {
    int g = blockIdx.x;
    int t = threadIdx.x;
    int beg = gstart[g];
    int end = gstart[g + 1];
    float sum = 0.0f;
    for (int i = beg; i < end; i++) sum += h[(size_t)i * HID + t];
    float c = (float)(end - beg);
    pooled[g * HID + t] = sum / fmaxf(c, 1.0f);
}

__global__ void out_gemm_kernel(const float* __restrict__ pooled, const float* __restrict__ W,
                                const float* __restrict__ b, float* __restrict__ out) {
    int idx = blockIdx.x * blockDim.x + threadIdx.x;
    if (idx >= NGRAPH * NCLS) return;
    int g = idx >> 4;
    int c = idx & 15;
    float s = b[c];
#pragma unroll 8
    for (int k = 0; k < HID; k++) s += pooled[g * HID + k] * W[k * NCLS + c];
    out[idx] = s;
}

// ---------------- launch ----------------
extern "C" void kernel_launch(void* const* d_in, const int* in_sizes, int n_in,
                              void* d_out, int out_size) {
    const float* x     = (const float*)d_in[0];
    const void*  ei    = d_in[1];
    const void*  batch = d_in[2];
    const float* W_in  = (const float*)d_in[3];
    const float* b_in  = (const float*)d_in[4];
    const float* W1    = (const float*)d_in[5];
    const float* b1    = (const float*)d_in[6];
    const float* W2    = (const float*)d_in[7];
    const float* b2    = (const float*)d_in[8];
    const float* W_out = (const float*)d_in[9];
    const float* b_out = (const float*)d_in[10];

    const int N = in_sizes[0] / INDIM;
    const int E = in_sizes[1] / 2;

    float *bufA, *dinv, *pool;
    __nv_bfloat16* bufH;
    int *indeg, *row_ptr, *cursor, *csr_src, *gstart, *localscan;
    cudaGetSymbolAddress((void**)&bufA, g_bufA);
    cudaGetSymbolAddress((void**)&bufH, g_bufH);
    cudaGetSymbolAddress((void**)&dinv, g_dinv);
    cudaGetSymbolAddress((void**)&pool, g_pool);
    cudaGetSymbolAddress((void**)&indeg, g_indeg);
    cudaGetSymbolAddress((void**)&row_ptr, g_row_ptr);
    cudaGetSymbolAddress((void**)&cursor, g_cursor);
    cudaGetSymbolAddress((void**)&csr_src, g_csr_src);
    cudaGetSymbolAddress((void**)&gstart, g_gstart);
    cudaGetSymbolAddress((void**)&localscan, g_localscan);

    detect_dtype_kernel<<<1, 256>>>((const int*)ei, 4096);

    zero_int_kernel<<<(N + 255) / 256, 256>>>(indeg, N);
    hist_dst_kernel<<<(E + 255) / 256, 256>>>(ei, E, indeg);
    gstart_binsearch_kernel<<<1, NGRAPH + 1>>>(batch, N, gstart);

    const int nb = (N + 1023) / 1024;
    scan_local_kernel<<<nb, 1024>>>(indeg, localscan, N);
    scan_blocksums_kernel<<<1, 64>>>(nb);
    scan_finalize_kernel<<<(N + 255) / 256, 256>>>(indeg, localscan, row_ptr, cursor, dinv, N);
    fill_csr_kernel<<<(E + 255) / 256, 256>>>(ei, E, cursor, csr_src);

    dim3 ggrid(HID / BN, (N + BM - 1) / BM);

    // input layer: bufA = x @ W_in + b_in (fp32)
    tf32gemm_kernel<<<ggrid, 256>>>(x, W_in, bufA, nullptr, N, INDIM, b_in, nullptr);

    // layer 1: bufH = bf16(dinv * (bufA @ W1)); bufA = relu(dinv*(sum+self)+b1)
    tf32gemm_kernel<<<ggrid, 256>>>(bufA, W1, nullptr, bufH, N, HID, nullptr, dinv);
    gather_kernel<<<(N * 32 + 255) / 256, 256>>>(bufH, bufA, row_ptr, csr_src, dinv, b1, N);

    // layer 2
    tf32gemm_kernel<<<ggrid, 256>>>(bufA, W2, nullptr, bufH, N, HID, nullptr, dinv);
    gather_kernel<<<(N * 32 + 255) / 256, 256>>>(bufH, bufA, row_ptr, csr_src, dinv, b2, N);

    pool_mean_kernel<<<NGRAPH, HID>>>(bufA, gstart, pool);
    out_gemm_kernel<<<(NGRAPH * NCLS + 255) / 256, 256>>>(pool, W_out, b_out, (float*)d_out);
}

// round 6
// speedup vs baseline: 1.3405x; 1.3405x over previous
#include <cuda_runtime.h>
#include <cuda_bf16.h>
#include <cstdint>

// Problem constants
#define NNODES 50000
#define NEDGES 800000
#define INDIM  128
#define HID    256
#define NGRAPH 128
#define NCLS   16

// ---------------- device scratch ----------------
__device__ float          g_bufA[NNODES * HID];   // fp32 activations
__device__ __nv_bfloat16  g_bufH[NNODES * HID];   // bf16 h' (messages)
__device__ float g_dinv[NNODES];
__device__ int   g_indeg[NNODES];
__device__ int   g_row_ptr[NNODES + 1];
__device__ int   g_cursor[NNODES];
__device__ int   g_csr_src[NEDGES];
__device__ int   g_localscan[NNODES];
__device__ int   g_blocksum[64];
__device__ int   g_blockoff[64];
__device__ float g_pool[NGRAPH * HID];
__device__ int   g_is64;

__device__ __forceinline__ int get_idx(const void* p, int i, int is64) {
    if (is64) return (int)((const long long*)p)[i];
    return ((const int*)p)[i];
}

__device__ __forceinline__ uint32_t f2tf32(float f) {
    uint32_t u;
    asm("cvt.rna.tf32.f32 %0, %1;" : "=r"(u) : "f"(f));
    return u;
}

__device__ __forceinline__ void addbf16x8(float* acc, uint4 u) {
    const __nv_bfloat162* p = reinterpret_cast<const __nv_bfloat162*>(&u);
#pragma unroll
    for (int q = 0; q < 4; q++) {
        float2 f = __bfloat1622float2(p[q]);
        acc[2 * q] += f.x;
        acc[2 * q + 1] += f.y;
    }
}

// ---------------- dtype detection ----------------
__global__ void detect_dtype_kernel(const int* __restrict__ w, int nOddSamples) {
    __shared__ int found;
    if (threadIdx.x == 0) found = 0;
    __syncthreads();
    for (int i = threadIdx.x; i < nOddSamples; i += blockDim.x) {
        if (w[2 * i + 1] != 0) found = 1;
    }
    __syncthreads();
    if (threadIdx.x == 0) g_is64 = found ? 0 : 1;
}

// ---------------- preprocessing ----------------
__global__ void zero_int_kernel(int* p, int n) {
    int i = blockIdx.x * blockDim.x + threadIdx.x;
    if (i < n) p[i] = 0;
}

__global__ void hist_dst_kernel(const void* __restrict__ ei, int E, int* __restrict__ indeg) {
    int e = blockIdx.x * blockDim.x + threadIdx.x;
    if (e < E) {
        int d = get_idx(ei, E + e, g_is64);
        atomicAdd(&indeg[d], 1);
    }
}

__global__ void scan_local_kernel(const int* __restrict__ counts, int* __restrict__ localscan, int n) {
    __shared__ int s[1024];
    int tid = threadIdx.x;
    int i = blockIdx.x * 1024 + tid;
    int v = (i < n) ? counts[i] : 0;
    s[tid] = v;
    __syncthreads();
    for (int off = 1; off < 1024; off <<= 1) {
        int t = (tid >= off) ? s[tid - off] : 0;
        __syncthreads();
        s[tid] += t;
        __syncthreads();
    }
    if (i < n) localscan[i] = s[tid];
    if (tid == 1023) g_blocksum[blockIdx.x] = s[1023];
}

__global__ void scan_blocksums_kernel(int nb) {
    __shared__ int s[64];
    int tid = threadIdx.x;
    int v = (tid < nb) ? g_blocksum[tid] : 0;
    s[tid] = v;
    __syncthreads();
    for (int off = 1; off < 64; off <<= 1) {
        int t = (tid >= off) ? s[tid - off] : 0;
        __syncthreads();
        s[tid] += t;
        __syncthreads();
    }
    g_blockoff[tid] = s[tid] - v;
}

__global__ void scan_finalize_kernel(const int* __restrict__ counts, const int* __restrict__ localscan,
                                     int* __restrict__ row_ptr, int* __restrict__ cursor,
                                     float* __restrict__ dinv, int n) {
    int i = blockIdx.x * blockDim.x + threadIdx.x;
    if (i < n) {
        int cnt = counts[i];
        int incl = localscan[i] + g_blockoff[i >> 10];
        row_ptr[i + 1] = incl;
        cursor[i] = incl - cnt;
        dinv[i] = rsqrtf((float)cnt + 1.0f);
        if (i == 0) row_ptr[0] = 0;
    }
}

__global__ void fill_csr_kernel(const void* __restrict__ ei, int E,
                                int* __restrict__ cursor, int* __restrict__ csr_src) {
    int e = blockIdx.x * blockDim.x + threadIdx.x;
    if (e < E) {
        int is64 = g_is64;
        int d = get_idx(ei, E + e, is64);
        int s = get_idx(ei, e, is64);
        int pos = atomicAdd(&cursor[d], 1);
        csr_src[pos] = s;
    }
}

// ---------------- TF32 tensor-core GEMM ----------------
#define BM 128
#define BN 128
#define BK 16
#define AS_K 20
#define BS_N 136

__global__ __launch_bounds__(256, 2) void tf32gemm_kernel(
    const float* __restrict__ A, const float* __restrict__ B,
    float* __restrict__ C, __nv_bfloat16* __restrict__ Cbf,
    int M, int K, const float* __restrict__ bias, const float* __restrict__ scale) {
    __shared__ uint32_t As[BM * AS_K];
    __shared__ uint32_t Bs[BK * BS_N];

    const int tid = threadIdx.x;
    const int colBase = blockIdx.x * BN;
    const int rowBase = blockIdx.y * BM;

    const int wid = tid >> 5;
    const int lane = tid & 31;
    const int warpM = wid & 3;
    const int warpN = wid >> 2;
    const int g = lane >> 2;
    const int t4 = lane & 3;
    const int mB = warpM * 32;
    const int nB = warpN * 64;

    const int aRow0 = tid >> 2;
    const int aRow1 = 64 + (tid >> 2);
    const int aC = (tid & 3) * 4;
    const int bRow0 = tid >> 5;
    const int bRow1 = 8 + (tid >> 5);
    const int bCol = (tid & 31) * 4;

    int gr0 = rowBase + aRow0; gr0 = gr0 < M ? gr0 : M - 1;
    int gr1 = rowBase + aRow1; gr1 = gr1 < M ? gr1 : M - 1;
    const float* aPtr0 = A + (size_t)gr0 * K + aC;
    const float* aPtr1 = A + (size_t)gr1 * K + aC;
    const float* bPtr0 = B + (size_t)bRow0 * HID + colBase + bCol;
    const float* bPtr1 = B + (size_t)bRow1 * HID + colBase + bCol;

    float acc[2][8][4];
#pragma unroll
    for (int mt = 0; mt < 2; mt++)
#pragma unroll
        for (int nt = 0; nt < 8; nt++)
#pragma unroll
            for (int c = 0; c < 4; c++) acc[mt][nt][c] = 0.0f;

    const int nTiles = K / BK;

    float4 pa0 = *reinterpret_cast<const float4*>(aPtr0);
    float4 pa1 = *reinterpret_cast<const float4*>(aPtr1);
    float4 pb0 = *reinterpret_cast<const float4*>(bPtr0);
    float4 pb1 = *reinterpret_cast<const float4*>(bPtr1);

    for (int t = 0; t < nTiles; t++) {
        {
            uint4 ua0 = make_uint4(f2tf32(pa0.x), f2tf32(pa0.y), f2tf32(pa0.z), f2tf32(pa0.w));
            uint4 ua1 = make_uint4(f2tf32(pa1.x), f2tf32(pa1.y), f2tf32(pa1.z), f2tf32(pa1.w));
            uint4 ub0 = make_uint4(f2tf32(pb0.x), f2tf32(pb0.y), f2tf32(pb0.z), f2tf32(pb0.w));
            uint4 ub1 = make_uint4(f2tf32(pb1.x), f2tf32(pb1.y), f2tf32(pb1.z), f2tf32(pb1.w));
            *reinterpret_cast<uint4*>(&As[aRow0 * AS_K + aC]) = ua0;
            *reinterpret_cast<uint4*>(&As[aRow1 * AS_K + aC]) = ua1;
            *reinterpret_cast<uint4*>(&Bs[bRow0 * BS_N + bCol]) = ub0;
            *reinterpret_cast<uint4*>(&Bs[bRow1 * BS_N + bCol]) = ub1;
        }
        __syncthreads();

        if (t + 1 < nTiles) {
            int k0 = (t + 1) * BK;
            pa0 = *reinterpret_cast<const float4*>(aPtr0 + k0);
            pa1 = *reinterpret_cast<const float4*>(aPtr1 + k0);
            pb0 = *reinterpret_cast<const float4*>(bPtr0 + (size_t)k0 * HID);
            pb1 = *reinterpret_cast<const float4*>(bPtr1 + (size_t)k0 * HID);
        }

#pragma unroll
        for (int ks = 0; ks < BK; ks += 8) {
            uint32_t af[2][4];
#pragma unroll
            for (int mt = 0; mt < 2; mt++) {
                int m0 = mB + mt * 16 + g;
                af[mt][0] = As[m0 * AS_K + ks + t4];
                af[mt][1] = As[(m0 + 8) * AS_K + ks + t4];
                af[mt][2] = As[m0 * AS_K + ks + t4 + 4];
                af[mt][3] = As[(m0 + 8) * AS_K + ks + t4 + 4];
            }
            uint32_t bf[8][2];
#pragma unroll
            for (int nt = 0; nt < 8; nt++) {
                int n0 = nB + nt * 8 + g;
                bf[nt][0] = Bs[(ks + t4) * BS_N + n0];
                bf[nt][1] = Bs[(ks + t4 + 4) * BS_N + n0];
            }
#pragma unroll
            for (int mt = 0; mt < 2; mt++)
#pragma unroll
                for (int nt = 0; nt < 8; nt++) {
                    asm volatile(
                        "mma.sync.aligned.m16n8k8.row.col.f32.tf32.tf32.f32 "
                        "{%0,%1,%2,%3}, {%4,%5,%6,%7}, {%8,%9}, {%0,%1,%2,%3};"
                        : "+f"(acc[mt][nt][0]), "+f"(acc[mt][nt][1]),
                          "+f"(acc[mt][nt][2]), "+f"(acc[mt][nt][3])
                        : "r"(af[mt][0]), "r"(af[mt][1]), "r"(af[mt][2]), "r"(af[mt][3]),
                          "r"(bf[nt][0]), "r"(bf[nt][1]));
                }
        }
        __syncthreads();
    }

#pragma unroll
    for (int mt = 0; mt < 2; mt++) {
        int r0 = rowBase + mB + mt * 16 + g;
        int r1 = r0 + 8;
        float s0 = 1.0f, s1 = 1.0f;
        if (scale) {
            if (r0 < M) s0 = scale[r0];
            if (r1 < M) s1 = scale[r1];
        }
#pragma unroll
        for (int nt = 0; nt < 8; nt++) {
            int c = colBase + nB + nt * 8 + t4 * 2;
            float bx = 0.f, by = 0.f;
            if (bias) { bx = bias[c]; by = bias[c + 1]; }
            float v0x = acc[mt][nt][0] * s0 + bx;
            float v0y = acc[mt][nt][1] * s0 + by;
            float v1x = acc[mt][nt][2] * s1 + bx;
            float v1y = acc[mt][nt][3] * s1 + by;
            if (Cbf) {
                if (r0 < M) {
                    __nv_bfloat162 p = __floats2bfloat162_rn(v0x, v0y);
                    *reinterpret_cast<__nv_bfloat162*>(&Cbf[(size_t)r0 * HID + c]) = p;
                }
                if (r1 < M) {
                    __nv_bfloat162 p = __floats2bfloat162_rn(v1x, v1y);
                    *reinterpret_cast<__nv_bfloat162*>(&Cbf[(size_t)r1 * HID + c]) = p;
                }
            } else {
                if (r0 < M) {
                    float2 v = make_float2(v0x, v0y);
                    *reinterpret_cast<float2*>(&C[(size_t)r0 * HID + c]) = v;
                }
                if (r1 < M) {
                    float2 v = make_float2(v1x, v1y);
                    *reinterpret_cast<float2*>(&C[(size_t)r1 * HID + c]) = v;
                }
            }
        }
    }
}

// ---------------- gather (bf16 in, fp32 out), 4-edge unroll for MLP ----------------
__global__ void gather_kernel(const __nv_bfloat16* __restrict__ hp, float* __restrict__ out,
                              const int* __restrict__ row_ptr, const int* __restrict__ csr_src,
                              const float* __restrict__ dinv, const float* __restrict__ bias, int n) {
    int warp = (blockIdx.x * blockDim.x + threadIdx.x) >> 5;
    int lane = threadIdx.x & 31;
    if (warp >= n) return;
    int beg = row_ptr[warp];
    int end = row_ptr[warp + 1];
    const int colOff = lane * 8;

    float a0[8], a1[8];
#pragma unroll
    for (int j = 0; j < 8; j++) { a0[j] = 0.f; a1[j] = 0.f; }

    int e = beg;
    for (; e + 4 <= end; e += 4) {
        int s0 = csr_src[e];
        int s1 = csr_src[e + 1];
        int s2 = csr_src[e + 2];
        int s3 = csr_src[e + 3];
        uint4 u0 = __ldg(reinterpret_cast<const uint4*>(hp + (size_t)s0 * HID + colOff));
        uint4 u1 = __ldg(reinterpret_cast<const uint4*>(hp + (size_t)s1 * HID + colOff));
        uint4 u2 = __ldg(reinterpret_cast<const uint4*>(hp + (size_t)s2 * HID + colOff));
        uint4 u3 = __ldg(reinterpret_cast<const uint4*>(hp + (size_t)s3 * HID + colOff));
        addbf16x8(a0, u0);
        addbf16x8(a1, u1);
        addbf16x8(a0, u2);
        addbf16x8(a1, u3);
    }
    if (e + 2 <= end) {
        int s0 = csr_src[e];
        int s1 = csr_src[e + 1];
        uint4 u0 = __ldg(reinterpret_cast<const uint4*>(hp + (size_t)s0 * HID + colOff));
        uint4 u1 = __ldg(reinterpret_cast<const uint4*>(hp + (size_t)s1 * HID + colOff));
        addbf16x8(a0, u0);
        addbf16x8(a1, u1);
        e += 2;
    }
    if (e < end) {
        int s0 = csr_src[e];
        uint4 u0 = __ldg(reinterpret_cast<const uint4*>(hp + (size_t)s0 * HID + colOff));
        addbf16x8(a0, u0);
    }
    // self contribution
    {
        uint4 u = *reinterpret_cast<const uint4*>(hp + (size_t)warp * HID + colOff);
        addbf16x8(a1, u);
    }

    float dv = dinv[warp];
    float4 b0 = *reinterpret_cast<const float4*>(bias + colOff);
    float4 b1 = *reinterpret_cast<const float4*>(bias + colOff + 4);
    float4 o0, o1;
    o0.x = fmaxf(dv * (a0[0] + a1[0]) + b0.x, 0.f);
    o0.y = fmaxf(dv * (a0[1] + a1[1]) + b0.y, 0.f);
    o0.z = fmaxf(dv * (a0[2] + a1[2]) + b0.z, 0.f);
    o0.w = fmaxf(dv * (a0[3] + a1[3]) + b0.w, 0.f);
    o1.x = fmaxf(dv * (a0[4] + a1[4]) + b1.x, 0.f);
    o1.y = fmaxf(dv * (a0[5] + a1[5]) + b1.y, 0.f);
    o1.z = fmaxf(dv * (a0[6] + a1[6]) + b1.z, 0.f);
    o1.w = fmaxf(dv * (a0[7] + a1[7]) + b1.w, 0.f);

    float* outrow = out + (size_t)warp * HID + colOff;
    *reinterpret_cast<float4*>(outrow) = o0;
    *reinterpret_cast<float4*>(outrow + 4) = o1;
}

// ---------------- pooling (inline per-block binary search; batch sorted) ----------------
__global__ void pool_mean_kernel(const float* __restrict__ h, const void* __restrict__ batch,
                                 int n, float* __restrict__ pooled) {
    __shared__ int sRange[2];
    int g = blockIdx.x;
    if (threadIdx.x < 2) {
        int target = g + threadIdx.x;
        int is64 = g_is64;
        int lo = 0, hi = n;
        while (lo < hi) {
            int mid = (lo + hi) >> 1;
            if (get_idx(batch, mid, is64) < target) lo = mid + 1; else hi = mid;
        }
        sRange[threadIdx.x] = lo;
    }
    __syncthreads();
    int beg = sRange[0];
    int end = sRange[1];
    float sum = 0.0f;
    for (int i = beg; i < end; i++) sum += h[(size_t)i * HID + threadIdx.x];
    float c = (float)(end - beg);
    pooled[g * HID + threadIdx.x] = sum / fmaxf(c, 1.0f);
}

__global__ void out_gemm_kernel(const float* __restrict__ pooled, const float* __restrict__ W,
                                const float* __restrict__ b, float* __restrict__ out) {
    int idx = blockIdx.x * blockDim.x + threadIdx.x;
    if (idx >= NGRAPH * NCLS) return;
    int g = idx >> 4;
    int c = idx & 15;
    float s = b[c];
#pragma unroll 8
    for (int k = 0; k < HID; k++) s += pooled[g * HID + k] * W[k * NCLS + c];
    out[idx] = s;
}

// ---------------- launch ----------------
extern "C" void kernel_launch(void* const* d_in, const int* in_sizes, int n_in,
                              void* d_out, int out_size) {
    const float* x     = (const float*)d_in[0];
    const void*  ei    = d_in[1];
    const void*  batch = d_in[2];
    const float* W_in  = (const float*)d_in[3];
    const float* b_in  = (const float*)d_in[4];
    const float* W1    = (const float*)d_in[5];
    const float* b1    = (const float*)d_in[6];
    const float* W2    = (const float*)d_in[7];
    const float* b2    = (const float*)d_in[8];
    const float* W_out = (const float*)d_in[9];
    const float* b_out = (const float*)d_in[10];

    const int N = in_sizes[0] / INDIM;
    const int E = in_sizes[1] / 2;

    float *bufA, *dinv, *pool;
    __nv_bfloat16* bufH;
    int *indeg, *row_ptr, *cursor, *csr_src, *localscan;
    cudaGetSymbolAddress((void**)&bufA, g_bufA);
    cudaGetSymbolAddress((void**)&bufH, g_bufH);
    cudaGetSymbolAddress((void**)&dinv, g_dinv);
    cudaGetSymbolAddress((void**)&pool, g_pool);
    cudaGetSymbolAddress((void**)&indeg, g_indeg);
    cudaGetSymbolAddress((void**)&row_ptr, g_row_ptr);
    cudaGetSymbolAddress((void**)&cursor, g_cursor);
    cudaGetSymbolAddress((void**)&csr_src, g_csr_src);
    cudaGetSymbolAddress((void**)&localscan, g_localscan);

    detect_dtype_kernel<<<1, 256>>>((const int*)ei, 4096);

    zero_int_kernel<<<(N + 255) / 256, 256>>>(indeg, N);
    hist_dst_kernel<<<(E + 255) / 256, 256>>>(ei, E, indeg);

    const int nb = (N + 1023) / 1024;
    scan_local_kernel<<<nb, 1024>>>(indeg, localscan, N);
    scan_blocksums_kernel<<<1, 64>>>(nb);
    scan_finalize_kernel<<<(N + 255) / 256, 256>>>(indeg, localscan, row_ptr, cursor, dinv, N);
    fill_csr_kernel<<<(E + 255) / 256, 256>>>(ei, E, cursor, csr_src);

    dim3 ggrid(HID / BN, (N + BM - 1) / BM);

    // input layer: bufA = x @ W_in + b_in (fp32)
    tf32gemm_kernel<<<ggrid, 256>>>(x, W_in, bufA, nullptr, N, INDIM, b_in, nullptr);

    // layer 1
    tf32gemm_kernel<<<ggrid, 256>>>(bufA, W1, nullptr, bufH, N, HID, nullptr, dinv);
    gather_kernel<<<(N * 32 + 255) / 256, 256>>>(bufH, bufA, row_ptr, csr_src, dinv, b1, N);

    // layer 2
    tf32gemm_kernel<<<ggrid, 256>>>(bufA, W2, nullptr, bufH, N, HID, nullptr, dinv);
    gather_kernel<<<(N * 32 + 255) / 256, 256>>>(bufH, bufA, row_ptr, csr_src, dinv, b2, N);

    pool_mean_kernel<<<NGRAPH, HID>>>(bufA, batch, N, pool);
    out_gemm_kernel<<<(NGRAPH * NCLS + 255) / 256, 256>>>(pool, W_out, b_out, (float*)d_out);
}

// round 8
// speedup vs baseline: 1.5025x; 1.1209x over previous
#include <cuda_runtime.h>
#include <cuda_bf16.h>
#include <cstdint>

// Problem constants
#define NNODES 50000
#define NEDGES 800000
#define INDIM  128
#define HID    256
#define NGRAPH 128
#define NCLS   16

// ---------------- device scratch ----------------
__device__ float          g_bufA[NNODES * HID];
__device__ __nv_bfloat16  g_bufH[NNODES * HID];
__device__ float g_dinv[NNODES];
__device__ int   g_indeg[NNODES];
__device__ int   g_row_ptr[NNODES + 1];
__device__ int   g_cursor[NNODES];
__device__ int   g_csr_src[NEDGES];
__device__ int   g_localscan[NNODES];
__device__ int   g_blocksum[64];
__device__ int   g_blockoff[64];
__device__ float g_pool[NGRAPH * HID];
__device__ int   g_is64;

__device__ __forceinline__ int get_idx(const void* p, int i, int is64) {
    if (is64) return (int)((const long long*)p)[i];
    return ((const int*)p)[i];
}

__device__ __forceinline__ void cp_async16(uint32_t saddr, const void* gptr) {
    asm volatile("cp.async.cg.shared.global [%0], [%1], 16;" :: "r"(saddr), "l"(gptr));
}
__device__ __forceinline__ void cp_commit() {
    asm volatile("cp.async.commit_group;");
}
template <int N>
__device__ __forceinline__ void cp_wait() {
    asm volatile("cp.async.wait_group %0;" :: "n"(N));
}

// round fp32 bits to tf32 (round-to-nearest) in-register
__device__ __forceinline__ uint32_t rna_tf32(uint32_t bits) {
    uint32_t u;
    asm("cvt.rna.tf32.f32 %0, %1;" : "=r"(u) : "f"(__uint_as_float(bits)));
    return u;
}

__device__ __forceinline__ void addbf16x8(float* acc, uint4 u) {
    const __nv_bfloat162* p = reinterpret_cast<const __nv_bfloat162*>(&u);
#pragma unroll
    for (int q = 0; q < 4; q++) {
        float2 f = __bfloat1622float2(p[q]);
        acc[2 * q] += f.x;
        acc[2 * q + 1] += f.y;
    }
}

// ---------------- dtype detection ----------------
__global__ void detect_dtype_kernel(const int* __restrict__ w, int nOddSamples) {
    __shared__ int found;
    if (threadIdx.x == 0) found = 0;
    __syncthreads();
    for (int i = threadIdx.x; i < nOddSamples; i += blockDim.x) {
        if (w[2 * i + 1] != 0) found = 1;
    }
    __syncthreads();
    if (threadIdx.x == 0) g_is64 = found ? 0 : 1;
}

// ---------------- preprocessing ----------------
__global__ void hist_dst_kernel(const void* __restrict__ ei, int E, int* __restrict__ indeg) {
    int e = blockIdx.x * blockDim.x + threadIdx.x;
    if (e < E) {
        int d = get_idx(ei, E + e, g_is64);
        atomicAdd(&indeg[d], 1);
    }
}

__global__ void scan_local_kernel(const int* __restrict__ counts, int* __restrict__ localscan, int n) {
    __shared__ int s[1024];
    int tid = threadIdx.x;
    int i = blockIdx.x * 1024 + tid;
    int v = (i < n) ? counts[i] : 0;
    s[tid] = v;
    __syncthreads();
    for (int off = 1; off < 1024; off <<= 1) {
        int t = (tid >= off) ? s[tid - off] : 0;
        __syncthreads();
        s[tid] += t;
        __syncthreads();
    }
    if (i < n) localscan[i] = s[tid];
    if (tid == 1023) g_blocksum[blockIdx.x] = s[1023];
}

__global__ void scan_blocksums_kernel(int nb) {
    __shared__ int s[64];
    int tid = threadIdx.x;
    int v = (tid < nb) ? g_blocksum[tid] : 0;
    s[tid] = v;
    __syncthreads();
    for (int off = 1; off < 64; off <<= 1) {
        int t = (tid >= off) ? s[tid - off] : 0;
        __syncthreads();
        s[tid] += t;
        __syncthreads();
    }
    g_blockoff[tid] = s[tid] - v;
}

__global__ void scan_finalize_kernel(const int* __restrict__ counts, const int* __restrict__ localscan,
                                     int* __restrict__ row_ptr, int* __restrict__ cursor,
                                     float* __restrict__ dinv, int n) {
    int i = blockIdx.x * blockDim.x + threadIdx.x;
    if (i < n) {
        int cnt = counts[i];
        int incl = localscan[i] + g_blockoff[i >> 10];
        row_ptr[i + 1] = incl;
        cursor[i] = incl - cnt;
        dinv[i] = rsqrtf((float)cnt + 1.0f);
        if (i == 0) row_ptr[0] = 0;
    }
}

__global__ void fill_csr_kernel(const void* __restrict__ ei, int E,
                                int* __restrict__ cursor, int* __restrict__ csr_src) {
    int e = blockIdx.x * blockDim.x + threadIdx.x;
    if (e < E) {
        int is64 = g_is64;
        int d = get_idx(ei, E + e, is64);
        int s = get_idx(ei, e, is64);
        int pos = atomicAdd(&cursor[d], 1);
        csr_src[pos] = s;
    }
}

// ---------------- TF32 GEMM: cp.async double buffering + rna rounding on fragments ----------------
#define BM 128
#define BN 128
#define BK 16
#define AS_K 20
#define BS_N 136

__global__ __launch_bounds__(256, 2) void tf32gemm_kernel(
    const float* __restrict__ A, const float* __restrict__ B,
    float* __restrict__ C, __nv_bfloat16* __restrict__ Cbf,
    int M, int K, const float* __restrict__ bias, const float* __restrict__ scale) {
    __shared__ uint32_t As[2][BM * AS_K];
    __shared__ uint32_t Bs[2][BK * BS_N];

    const int tid = threadIdx.x;
    const int colBase = blockIdx.x * BN;
    const int rowBase = blockIdx.y * BM;

    const int wid = tid >> 5;
    const int lane = tid & 31;
    const int warpM = wid & 3;
    const int warpN = wid >> 2;
    const int g = lane >> 2;
    const int t4 = lane & 3;
    const int mB = warpM * 32;
    const int nB = warpN * 64;

    const int aRow0 = tid >> 2;
    const int aRow1 = 64 + (tid >> 2);
    const int aC = (tid & 3) * 4;
    const int bRow0 = tid >> 5;
    const int bRow1 = 8 + (tid >> 5);
    const int bCol = (tid & 31) * 4;

    int gr0 = rowBase + aRow0; gr0 = gr0 < M ? gr0 : M - 1;
    int gr1 = rowBase + aRow1; gr1 = gr1 < M ? gr1 : M - 1;
    const float* aPtr0 = A + (size_t)gr0 * K + aC;
    const float* aPtr1 = A + (size_t)gr1 * K + aC;
    const float* bPtr0 = B + (size_t)bRow0 * HID + colBase + bCol;
    const float* bPtr1 = B + (size_t)bRow1 * HID + colBase + bCol;

    const uint32_t asBytes = BM * AS_K * 4;
    const uint32_t bsBytes = BK * BS_N * 4;
    uint32_t sa0 = (uint32_t)__cvta_generic_to_shared(&As[0][aRow0 * AS_K + aC]);
    uint32_t sa1 = (uint32_t)__cvta_generic_to_shared(&As[0][aRow1 * AS_K + aC]);
    uint32_t sb0 = (uint32_t)__cvta_generic_to_shared(&Bs[0][bRow0 * BS_N + bCol]);
    uint32_t sb1 = (uint32_t)__cvta_generic_to_shared(&Bs[0][bRow1 * BS_N + bCol]);

    float acc[2][8][4];
#pragma unroll
    for (int mt = 0; mt < 2; mt++)
#pragma unroll
        for (int nt = 0; nt < 8; nt++)
#pragma unroll
            for (int c = 0; c < 4; c++) acc[mt][nt][c] = 0.0f;

    const int nTiles = K / BK;

    cp_async16(sa0, aPtr0);
    cp_async16(sa1, aPtr1);
    cp_async16(sb0, bPtr0);
    cp_async16(sb1, bPtr1);
    cp_commit();
    if (nTiles > 1) {
        cp_async16(sa0 + asBytes, aPtr0 + BK);
        cp_async16(sa1 + asBytes, aPtr1 + BK);
        cp_async16(sb0 + bsBytes, bPtr0 + (size_t)BK * HID);
        cp_async16(sb1 + bsBytes, bPtr1 + (size_t)BK * HID);
        cp_commit();
    }

    for (int t = 0; t < nTiles; t++) {
        if (t + 1 < nTiles) cp_wait<1>(); else cp_wait<0>();
        __syncthreads();

        const int st = t & 1;
        const uint32_t* AsS = As[st];
        const uint32_t* BsS = Bs[st];

#pragma unroll
        for (int ks = 0; ks < BK; ks += 8) {
            uint32_t af[2][4];
#pragma unroll
            for (int mt = 0; mt < 2; mt++) {
                int m0 = mB + mt * 16 + g;
                af[mt][0] = rna_tf32(AsS[m0 * AS_K + ks + t4]);
                af[mt][1] = rna_tf32(AsS[(m0 + 8) * AS_K + ks + t4]);
                af[mt][2] = rna_tf32(AsS[m0 * AS_K + ks + t4 + 4]);
                af[mt][3] = rna_tf32(AsS[(m0 + 8) * AS_K + ks + t4 + 4]);
            }
            uint32_t bf[8][2];
#pragma unroll
            for (int nt = 0; nt < 8; nt++) {
                int n0 = nB + nt * 8 + g;
                bf[nt][0] = rna_tf32(BsS[(ks + t4) * BS_N + n0]);
                bf[nt][1] = rna_tf32(BsS[(ks + t4 + 4) * BS_N + n0]);
            }
#pragma unroll
            for (int mt = 0; mt < 2; mt++)
#pragma unroll
                for (int nt = 0; nt < 8; nt++) {
                    asm volatile(
                        "mma.sync.aligned.m16n8k8.row.col.f32.tf32.tf32.f32 "
                        "{%0,%1,%2,%3}, {%4,%5,%6,%7}, {%8,%9}, {%0,%1,%2,%3};"
                        : "+f"(acc[mt][nt][0]), "+f"(acc[mt][nt][1]),
                          "+f"(acc[mt][nt][2]), "+f"(acc[mt][nt][3])
                        : "r"(af[mt][0]), "r"(af[mt][1]), "r"(af[mt][2]), "r"(af[mt][3]),
                          "r"(bf[nt][0]), "r"(bf[nt][1]));
                }
        }
        __syncthreads();

        if (t + 2 < nTiles) {
            int k0 = (t + 2) * BK;
            uint32_t off = st ? asBytes : 0;
            uint32_t offB = st ? bsBytes : 0;
            cp_async16(sa0 + off, aPtr0 + k0);
            cp_async16(sa1 + off, aPtr1 + k0);
            cp_async16(sb0 + offB, bPtr0 + (size_t)k0 * HID);
            cp_async16(sb1 + offB, bPtr1 + (size_t)k0 * HID);
            cp_commit();
        }
    }

    // epilogue
#pragma unroll
    for (int mt = 0; mt < 2; mt++) {
        int r0 = rowBase + mB + mt * 16 + g;
        int r1 = r0 + 8;
        float s0 = 1.0f, s1 = 1.0f;
        if (scale) {
            if (r0 < M) s0 = scale[r0];
            if (r1 < M) s1 = scale[r1];
        }
#pragma unroll
        for (int nt = 0; nt < 8; nt++) {
            int c = colBase + nB + nt * 8 + t4 * 2;
            float bx = 0.f, by = 0.f;
            if (bias) { bx = bias[c]; by = bias[c + 1]; }
            float v0x = acc[mt][nt][0] * s0 + bx;
            float v0y = acc[mt][nt][1] * s0 + by;
            float v1x = acc[mt][nt][2] * s1 + bx;
            float v1y = acc[mt][nt][3] * s1 + by;
            if (Cbf) {
                if (r0 < M) {
                    __nv_bfloat162 p = __floats2bfloat162_rn(v0x, v0y);
                    *reinterpret_cast<__nv_bfloat162*>(&Cbf[(size_t)r0 * HID + c]) = p;
                }
                if (r1 < M) {
                    __nv_bfloat162 p = __floats2bfloat162_rn(v1x, v1y);
                    *reinterpret_cast<__nv_bfloat162*>(&Cbf[(size_t)r1 * HID + c]) = p;
                }
            } else {
                if (r0 < M) {
                    float2 v = make_float2(v0x, v0y);
                    *reinterpret_cast<float2*>(&C[(size_t)r0 * HID + c]) = v;
                }
                if (r1 < M) {
                    float2 v = make_float2(v1x, v1y);
                    *reinterpret_cast<float2*>(&C[(size_t)r1 * HID + c]) = v;
                }
            }
        }
    }
}

// ---------------- gather (bf16 in, fp32 out), 8-edge unroll ----------------
__global__ void gather_kernel(const __nv_bfloat16* __restrict__ hp, float* __restrict__ out,
                              const int* __restrict__ row_ptr, const int* __restrict__ csr_src,
                              const float* __restrict__ dinv, const float* __restrict__ bias, int n) {
    int warp = (blockIdx.x * blockDim.x + threadIdx.x) >> 5;
    int lane = threadIdx.x & 31;
    if (warp >= n) return;
    int beg = row_ptr[warp];
    int end = row_ptr[warp + 1];
    const int colOff = lane * 8;

    float a0[8], a1[8];
#pragma unroll
    for (int j = 0; j < 8; j++) { a0[j] = 0.f; a1[j] = 0.f; }

    int e = beg;
    for (; e + 8 <= end; e += 8) {
        uint4 u[8];
#pragma unroll
        for (int q = 0; q < 8; q++) {
            int s = csr_src[e + q];
            u[q] = __ldg(reinterpret_cast<const uint4*>(hp + (size_t)s * HID + colOff));
        }
#pragma unroll
        for (int q = 0; q < 8; q++) addbf16x8((q & 1) ? a1 : a0, u[q]);
    }
    if (e + 4 <= end) {
        uint4 u[4];
#pragma unroll
        for (int q = 0; q < 4; q++) {
            int s = csr_src[e + q];
            u[q] = __ldg(reinterpret_cast<const uint4*>(hp + (size_t)s * HID + colOff));
        }
#pragma unroll
        for (int q = 0; q < 4; q++) addbf16x8((q & 1) ? a1 : a0, u[q]);
        e += 4;
    }
    if (e + 2 <= end) {
        int s0 = csr_src[e];
        int s1 = csr_src[e + 1];
        uint4 u0 = __ldg(reinterpret_cast<const uint4*>(hp + (size_t)s0 * HID + colOff));
        uint4 u1 = __ldg(reinterpret_cast<const uint4*>(hp + (size_t)s1 * HID + colOff));
        addbf16x8(a0, u0);
        addbf16x8(a1, u1);
        e += 2;
    }
    if (e < end) {
        int s0 = csr_src[e];
        uint4 u0 = __ldg(reinterpret_cast<const uint4*>(hp + (size_t)s0 * HID + colOff));
        addbf16x8(a0, u0);
    }
    {
        uint4 u = *reinterpret_cast<const uint4*>(hp + (size_t)warp * HID + colOff);
        addbf16x8(a1, u);
    }

    float dv = dinv[warp];
    float4 b0 = *reinterpret_cast<const float4*>(bias + colOff);
    float4 b1 = *reinterpret_cast<const float4*>(bias + colOff + 4);
    float4 o0, o1;
    o0.x = fmaxf(dv * (a0[0] + a1[0]) + b0.x, 0.f);
    o0.y = fmaxf(dv * (a0[1] + a1[1]) + b0.y, 0.f);
    o0.z = fmaxf(dv * (a0[2] + a1[2]) + b0.z, 0.f);
    o0.w = fmaxf(dv * (a0[3] + a1[3]) + b0.w, 0.f);
    o1.x = fmaxf(dv * (a0[4] + a1[4]) + b1.x, 0.f);
    o1.y = fmaxf(dv * (a0[5] + a1[5]) + b1.y, 0.f);
    o1.z = fmaxf(dv * (a0[6] + a1[6]) + b1.z, 0.f);
    o1.w = fmaxf(dv * (a0[7] + a1[7]) + b1.w, 0.f);

    float* outrow = out + (size_t)warp * HID + colOff;
    *reinterpret_cast<float4*>(outrow) = o0;
    *reinterpret_cast<float4*>(outrow + 4) = o1;
}

// ---------------- pooling (inline per-block binary search; batch sorted) ----------------
__global__ void pool_mean_kernel(const float* __restrict__ h, const void* __restrict__ batch,
                                 int n, float* __restrict__ pooled) {
    __shared__ int sRange[2];
    int g = blockIdx.x;
    if (threadIdx.x < 2) {
        int target = g + threadIdx.x;
        int is64 = g_is64;
        int lo = 0, hi = n;
        while (lo < hi) {
            int mid = (lo + hi) >> 1;
            if (get_idx(batch, mid, is64) < target) lo = mid + 1; else hi = mid;
        }
        sRange[threadIdx.x] = lo;
    }
    __syncthreads();
    int beg = sRange[0];
    int end = sRange[1];
    float sum = 0.0f;
    for (int i = beg; i < end; i++) sum += h[(size_t)i * HID + threadIdx.x];
    float c = (float)(end - beg);
    pooled[g * HID + threadIdx.x] = sum / fmaxf(c, 1.0f);
}

__global__ void out_gemm_kernel(const float* __restrict__ pooled, const float* __restrict__ W,
                                const float* __restrict__ b, float* __restrict__ out) {
    int idx = blockIdx.x * blockDim.x + threadIdx.x;
    if (idx >= NGRAPH * NCLS) return;
    int g = idx >> 4;
    int c = idx & 15;
    float s = b[c];
#pragma unroll 8
    for (int k = 0; k < HID; k++) s += pooled[g * HID + k] * W[k * NCLS + c];
    out[idx] = s;
}

// ---------------- launch ----------------
extern "C" void kernel_launch(void* const* d_in, const int* in_sizes, int n_in,
                              void* d_out, int out_size) {
    const float* x     = (const float*)d_in[0];
    const void*  ei    = d_in[1];
    const void*  batch = d_in[2];
    const float* W_in  = (const float*)d_in[3];
    const float* b_in  = (const float*)d_in[4];
    const float* W1    = (const float*)d_in[5];
    const float* b1    = (const float*)d_in[6];
    const float* W2    = (const float*)d_in[7];
    const float* b2    = (const float*)d_in[8];
    const float* W_out = (const float*)d_in[9];
    const float* b_out = (const float*)d_in[10];

    const int N = in_sizes[0] / INDIM;
    const int E = in_sizes[1] / 2;

    float *bufA, *dinv, *pool;
    __nv_bfloat16* bufH;
    int *indeg, *row_ptr, *cursor, *csr_src, *localscan;
    cudaGetSymbolAddress((void**)&bufA, g_bufA);
    cudaGetSymbolAddress((void**)&bufH, g_bufH);
    cudaGetSymbolAddress((void**)&dinv, g_dinv);
    cudaGetSymbolAddress((void**)&pool, g_pool);
    cudaGetSymbolAddress((void**)&indeg, g_indeg);
    cudaGetSymbolAddress((void**)&row_ptr, g_row_ptr);
    cudaGetSymbolAddress((void**)&cursor, g_cursor);
    cudaGetSymbolAddress((void**)&csr_src, g_csr_src);
    cudaGetSymbolAddress((void**)&localscan, g_localscan);

    detect_dtype_kernel<<<1, 256>>>((const int*)ei, 4096);

    cudaMemsetAsync(indeg, 0, N * sizeof(int), 0);
    hist_dst_kernel<<<(E + 255) / 256, 256>>>(ei, E, indeg);

    const int nb = (N + 1023) / 1024;
    scan_local_kernel<<<nb, 1024>>>(indeg, localscan, N);
    scan_blocksums_kernel<<<1, 64>>>(nb);
    scan_finalize_kernel<<<(N + 255) / 256, 256>>>(indeg, localscan, row_ptr, cursor, dinv, N);
    fill_csr_kernel<<<(E + 255) / 256, 256>>>(ei, E, cursor, csr_src);

    dim3 ggrid(HID / BN, (N + BM - 1) / BM);

    tf32gemm_kernel<<<ggrid, 256>>>(x, W_in, bufA, nullptr, N, INDIM, b_in, nullptr);

    tf32gemm_kernel<<<ggrid, 256>>>(bufA, W1, nullptr, bufH, N, HID, nullptr, dinv);
    gather_kernel<<<(N * 32 + 255) / 256, 256>>>(bufH, bufA, row_ptr, csr_src, dinv, b1, N);

    tf32gemm_kernel<<<ggrid, 256>>>(bufA, W2, nullptr, bufH, N, HID, nullptr, dinv);
    gather_kernel<<<(N * 32 + 255) / 256, 256>>>(bufH, bufA, row_ptr, csr_src, dinv, b2, N);

    pool_mean_kernel<<<NGRAPH, HID>>>(bufA, batch, N, pool);
    out_gemm_kernel<<<(NGRAPH * NCLS + 255) / 256, 256>>>(pool, W_out, b_out, (float*)d_out);
}

// round 9
// speedup vs baseline: 1.5433x; 1.0272x over previous
#include <cuda_runtime.h>
#include <cuda_bf16.h>
#include <cstdint>

// Problem constants
#define NNODES 50000
#define NEDGES 800000
#define INDIM  128
#define HID    256
#define NGRAPH 128
#define NCLS   16

// ---------------- device scratch ----------------
__device__ float          g_bufA[NNODES * HID];
__device__ __nv_bfloat16  g_bufH[NNODES * HID];
__device__ float g_dinv[NNODES];
__device__ int   g_indeg[NNODES];
__device__ int   g_row_ptr[NNODES + 1];
__device__ int   g_cursor[NNODES];
__device__ int   g_csr_src[NEDGES];
__device__ int   g_localscan[NNODES];
__device__ int   g_blocksum[64];
__device__ float g_pool[NGRAPH * HID];
__device__ int   g_is64;

__device__ __forceinline__ int get_idx(const void* p, int i, int is64) {
    if (is64) return (int)((const long long*)p)[i];
    return ((const int*)p)[i];
}

__device__ __forceinline__ void cp_async16(uint32_t saddr, const void* gptr) {
    asm volatile("cp.async.cg.shared.global [%0], [%1], 16;" :: "r"(saddr), "l"(gptr));
}
__device__ __forceinline__ void cp_commit() {
    asm volatile("cp.async.commit_group;");
}
template <int N>
__device__ __forceinline__ void cp_wait() {
    asm volatile("cp.async.wait_group %0;" :: "n"(N));
}

__device__ __forceinline__ uint32_t rna_tf32(uint32_t bits) {
    uint32_t u;
    asm("cvt.rna.tf32.f32 %0, %1;" : "=r"(u) : "f"(__uint_as_float(bits)));
    return u;
}

__device__ __forceinline__ void addbf16x8(float* acc, uint4 u) {
    const __nv_bfloat162* p = reinterpret_cast<const __nv_bfloat162*>(&u);
#pragma unroll
    for (int q = 0; q < 4; q++) {
        float2 f = __bfloat1622float2(p[q]);
        acc[2 * q] += f.x;
        acc[2 * q + 1] += f.y;
    }
}

// ---------------- dtype detection ----------------
__global__ void detect_dtype_kernel(const int* __restrict__ w, int nOddSamples) {
    __shared__ int found;
    if (threadIdx.x == 0) found = 0;
    __syncthreads();
    for (int i = threadIdx.x; i < nOddSamples; i += blockDim.x) {
        if (w[2 * i + 1] != 0) found = 1;
    }
    __syncthreads();
    if (threadIdx.x == 0) g_is64 = found ? 0 : 1;
}

// ---------------- preprocessing ----------------
__global__ void hist_dst_kernel(const void* __restrict__ ei, int E, int* __restrict__ indeg) {
    int e = blockIdx.x * blockDim.x + threadIdx.x;
    if (e < E) {
        int d = get_idx(ei, E + e, g_is64);
        atomicAdd(&indeg[d], 1);
    }
}

__global__ void scan_local_kernel(const int* __restrict__ counts, int* __restrict__ localscan, int n) {
    __shared__ int s[1024];
    int tid = threadIdx.x;
    int i = blockIdx.x * 1024 + tid;
    int v = (i < n) ? counts[i] : 0;
    s[tid] = v;
    __syncthreads();
    for (int off = 1; off < 1024; off <<= 1) {
        int t = (tid >= off) ? s[tid - off] : 0;
        __syncthreads();
        s[tid] += t;
        __syncthreads();
    }
    if (i < n) localscan[i] = s[tid];
    if (tid == 1023) g_blocksum[blockIdx.x] = s[1023];
}

// finalize: blocks are 256-wide so i>>10 is constant per block; thread 0 sums the prefix.
__global__ void scan_finalize_kernel(const int* __restrict__ counts, const int* __restrict__ localscan,
                                     int* __restrict__ row_ptr, int* __restrict__ cursor,
                                     float* __restrict__ dinv, int n) {
    __shared__ int sOff;
    int bucket = blockIdx.x >> 2;   // (blockIdx.x*256)>>10
    if (threadIdx.x == 0) {
        int off = 0;
        for (int j = 0; j < bucket; j++) off += g_blocksum[j];
        sOff = off;
    }
    __syncthreads();
    int i = blockIdx.x * blockDim.x + threadIdx.x;
    if (i < n) {
        int cnt = counts[i];
        int incl = localscan[i] + sOff;
        row_ptr[i + 1] = incl;
        cursor[i] = incl - cnt;
        dinv[i] = rsqrtf((float)cnt + 1.0f);
        if (i == 0) row_ptr[0] = 0;
    }
}

__global__ void fill_csr_kernel(const void* __restrict__ ei, int E,
                                int* __restrict__ cursor, int* __restrict__ csr_src) {
    int e = blockIdx.x * blockDim.x + threadIdx.x;
    if (e < E) {
        int is64 = g_is64;
        int d = get_idx(ei, E + e, is64);
        int s = get_idx(ei, e, is64);
        int pos = atomicAdd(&cursor[d], 1);
        csr_src[pos] = s;
    }
}

// ---------------- TF32 GEMM: persistent CTAs + cp.async double buffering ----------------
#define BM 128
#define BN 128
#define BK 16
#define AS_K 20
#define BS_N 136

__global__ __launch_bounds__(256, 2) void tf32gemm_kernel(
    const float* __restrict__ A, const float* __restrict__ B,
    float* __restrict__ C, __nv_bfloat16* __restrict__ Cbf,
    int M, int K, const float* __restrict__ bias, const float* __restrict__ scale) {
    __shared__ uint32_t As[2][BM * AS_K];
    __shared__ uint32_t Bs[2][BK * BS_N];

    const int tid = threadIdx.x;
    const int wid = tid >> 5;
    const int lane = tid & 31;
    const int warpM = wid & 3;
    const int warpN = wid >> 2;
    const int g = lane >> 2;
    const int t4 = lane & 3;
    const int mB = warpM * 32;
    const int nB = warpN * 64;

    const int aRow0 = tid >> 2;
    const int aRow1 = 64 + (tid >> 2);
    const int aC = (tid & 3) * 4;
    const int bRow0 = tid >> 5;
    const int bRow1 = 8 + (tid >> 5);
    const int bCol = (tid & 31) * 4;

    const uint32_t asBytes = BM * AS_K * 4;
    const uint32_t bsBytes = BK * BS_N * 4;
    const uint32_t sa0 = (uint32_t)__cvta_generic_to_shared(&As[0][aRow0 * AS_K + aC]);
    const uint32_t sa1 = (uint32_t)__cvta_generic_to_shared(&As[0][aRow1 * AS_K + aC]);
    const uint32_t sb0 = (uint32_t)__cvta_generic_to_shared(&Bs[0][bRow0 * BS_N + bCol]);
    const uint32_t sb1 = (uint32_t)__cvta_generic_to_shared(&Bs[0][bRow1 * BS_N + bCol]);

    const int nTiles = K / BK;
    const int numRowTiles = (M + BM - 1) / BM;
    const int numTiles = numRowTiles * (HID / BN);

    for (int bt = blockIdx.x; bt < numTiles; bt += gridDim.x) {
        const int rowBase = (bt >> 1) * BM;
        const int colBase = (bt & 1) * BN;

        int gr0 = rowBase + aRow0; gr0 = gr0 < M ? gr0 : M - 1;
        int gr1 = rowBase + aRow1; gr1 = gr1 < M ? gr1 : M - 1;
        const float* aPtr0 = A + (size_t)gr0 * K + aC;
        const float* aPtr1 = A + (size_t)gr1 * K + aC;
        const float* bPtr0 = B + (size_t)bRow0 * HID + colBase + bCol;
        const float* bPtr1 = B + (size_t)bRow1 * HID + colBase + bCol;

        float acc[2][8][4];
#pragma unroll
        for (int mt = 0; mt < 2; mt++)
#pragma unroll
            for (int nt = 0; nt < 8; nt++)
#pragma unroll
                for (int c = 0; c < 4; c++) acc[mt][nt][c] = 0.0f;

        cp_async16(sa0, aPtr0);
        cp_async16(sa1, aPtr1);
        cp_async16(sb0, bPtr0);
        cp_async16(sb1, bPtr1);
        cp_commit();
        if (nTiles > 1) {
            cp_async16(sa0 + asBytes, aPtr0 + BK);
            cp_async16(sa1 + asBytes, aPtr1 + BK);
            cp_async16(sb0 + bsBytes, bPtr0 + (size_t)BK * HID);
            cp_async16(sb1 + bsBytes, bPtr1 + (size_t)BK * HID);
            cp_commit();
        }

        for (int t = 0; t < nTiles; t++) {
            if (t + 1 < nTiles) cp_wait<1>(); else cp_wait<0>();
            __syncthreads();

            const int st = t & 1;
            const uint32_t* AsS = As[st];
            const uint32_t* BsS = Bs[st];

#pragma unroll
            for (int ks = 0; ks < BK; ks += 8) {
                uint32_t af[2][4];
#pragma unroll
                for (int mt = 0; mt < 2; mt++) {
                    int m0 = mB + mt * 16 + g;
                    af[mt][0] = rna_tf32(AsS[m0 * AS_K + ks + t4]);
                    af[mt][1] = rna_tf32(AsS[(m0 + 8) * AS_K + ks + t4]);
                    af[mt][2] = rna_tf32(AsS[m0 * AS_K + ks + t4 + 4]);
                    af[mt][3] = rna_tf32(AsS[(m0 + 8) * AS_K + ks + t4 + 4]);
                }
                uint32_t bf[8][2];
#pragma unroll
                for (int nt = 0; nt < 8; nt++) {
                    int n0 = nB + nt * 8 + g;
                    bf[nt][0] = rna_tf32(BsS[(ks + t4) * BS_N + n0]);
                    bf[nt][1] = rna_tf32(BsS[(ks + t4 + 4) * BS_N + n0]);
                }
#pragma unroll
                for (int mt = 0; mt < 2; mt++)
#pragma unroll
                    for (int nt = 0; nt < 8; nt++) {
                        asm volatile(
                            "mma.sync.aligned.m16n8k8.row.col.f32.tf32.tf32.f32 "
                            "{%0,%1,%2,%3}, {%4,%5,%6,%7}, {%8,%9}, {%0,%1,%2,%3};"
                            : "+f"(acc[mt][nt][0]), "+f"(acc[mt][nt][1]),
                              "+f"(acc[mt][nt][2]), "+f"(acc[mt][nt][3])
                            : "r"(af[mt][0]), "r"(af[mt][1]), "r"(af[mt][2]), "r"(af[mt][3]),
                              "r"(bf[nt][0]), "r"(bf[nt][1]));
                    }
            }
            __syncthreads();

            if (t + 2 < nTiles) {
                int k0 = (t + 2) * BK;
                uint32_t off = st ? asBytes : 0;
                uint32_t offB = st ? bsBytes : 0;
                cp_async16(sa0 + off, aPtr0 + k0);
                cp_async16(sa1 + off, aPtr1 + k0);
                cp_async16(sb0 + offB, bPtr0 + (size_t)k0 * HID);
                cp_async16(sb1 + offB, bPtr1 + (size_t)k0 * HID);
                cp_commit();
            }
        }

        // epilogue
#pragma unroll
        for (int mt = 0; mt < 2; mt++) {
            int r0 = rowBase + mB + mt * 16 + g;
            int r1 = r0 + 8;
            float s0 = 1.0f, s1 = 1.0f;
            if (scale) {
                if (r0 < M) s0 = scale[r0];
                if (r1 < M) s1 = scale[r1];
            }
#pragma unroll
            for (int nt = 0; nt < 8; nt++) {
                int c = colBase + nB + nt * 8 + t4 * 2;
                float bx = 0.f, by = 0.f;
                if (bias) { bx = bias[c]; by = bias[c + 1]; }
                float v0x = acc[mt][nt][0] * s0 + bx;
                float v0y = acc[mt][nt][1] * s0 + by;
                float v1x = acc[mt][nt][2] * s1 + bx;
                float v1y = acc[mt][nt][3] * s1 + by;
                if (Cbf) {
                    if (r0 < M) {
                        __nv_bfloat162 p = __floats2bfloat162_rn(v0x, v0y);
                        *reinterpret_cast<__nv_bfloat162*>(&Cbf[(size_t)r0 * HID + c]) = p;
                    }
                    if (r1 < M) {
                        __nv_bfloat162 p = __floats2bfloat162_rn(v1x, v1y);
                        *reinterpret_cast<__nv_bfloat162*>(&Cbf[(size_t)r1 * HID + c]) = p;
                    }
                } else {
                    if (r0 < M) {
                        float2 v = make_float2(v0x, v0y);
                        *reinterpret_cast<float2*>(&C[(size_t)r0 * HID + c]) = v;
                    }
                    if (r1 < M) {
                        float2 v = make_float2(v1x, v1y);
                        *reinterpret_cast<float2*>(&C[(size_t)r1 * HID + c]) = v;
                    }
                }
            }
        }
        __syncthreads();   // all reads of smem done before next tile's prologue
    }
}

// ---------------- gather (bf16 in, fp32 out), 8-edge unroll ----------------
__global__ void gather_kernel(const __nv_bfloat16* __restrict__ hp, float* __restrict__ out,
                              const int* __restrict__ row_ptr, const int* __restrict__ csr_src,
                              const float* __restrict__ dinv, const float* __restrict__ bias, int n) {
    int warp = (blockIdx.x * blockDim.x + threadIdx.x) >> 5;
    int lane = threadIdx.x & 31;
    if (warp >= n) return;
    int beg = row_ptr[warp];
    int end = row_ptr[warp + 1];
    const int colOff = lane * 8;

    float a0[8], a1[8];
#pragma unroll
    for (int j = 0; j < 8; j++) { a0[j] = 0.f; a1[j] = 0.f; }

    int e = beg;
    for (; e + 8 <= end; e += 8) {
        uint4 u[8];
#pragma unroll
        for (int q = 0; q < 8; q++) {
            int s = csr_src[e + q];
            u[q] = __ldg(reinterpret_cast<const uint4*>(hp + (size_t)s * HID + colOff));
        }
#pragma unroll
        for (int q = 0; q < 8; q++) addbf16x8((q & 1) ? a1 : a0, u[q]);
    }
    if (e + 4 <= end) {
        uint4 u[4];
#pragma unroll
        for (int q = 0; q < 4; q++) {
            int s = csr_src[e + q];
            u[q] = __ldg(reinterpret_cast<const uint4*>(hp + (size_t)s * HID + colOff));
        }
#pragma unroll
        for (int q = 0; q < 4; q++) addbf16x8((q & 1) ? a1 : a0, u[q]);
        e += 4;
    }
    if (e + 2 <= end) {
        int s0 = csr_src[e];
        int s1 = csr_src[e + 1];
        uint4 u0 = __ldg(reinterpret_cast<const uint4*>(hp + (size_t)s0 * HID + colOff));
        uint4 u1 = __ldg(reinterpret_cast<const uint4*>(hp + (size_t)s1 * HID + colOff));
        addbf16x8(a0, u0);
        addbf16x8(a1, u1);
        e += 2;
    }
    if (e < end) {
        int s0 = csr_src[e];
        uint4 u0 = __ldg(reinterpret_cast<const uint4*>(hp + (size_t)s0 * HID + colOff));
        addbf16x8(a0, u0);
    }
    {
        uint4 u = *reinterpret_cast<const uint4*>(hp + (size_t)warp * HID + colOff);
        addbf16x8(a1, u);
    }

    float dv = dinv[warp];
    float4 b0 = *reinterpret_cast<const float4*>(bias + colOff);
    float4 b1 = *reinterpret_cast<const float4*>(bias + colOff + 4);
    float4 o0, o1;
    o0.x = fmaxf(dv * (a0[0] + a1[0]) + b0.x, 0.f);
    o0.y = fmaxf(dv * (a0[1] + a1[1]) + b0.y, 0.f);
    o0.z = fmaxf(dv * (a0[2] + a1[2]) + b0.z, 0.f);
    o0.w = fmaxf(dv * (a0[3] + a1[3]) + b0.w, 0.f);
    o1.x = fmaxf(dv * (a0[4] + a1[4]) + b1.x, 0.f);
    o1.y = fmaxf(dv * (a0[5] + a1[5]) + b1.y, 0.f);
    o1.z = fmaxf(dv * (a0[6] + a1[6]) + b1.z, 0.f);
    o1.w = fmaxf(dv * (a0[7] + a1[7]) + b1.w, 0.f);

    float* outrow = out + (size_t)warp * HID + colOff;
    *reinterpret_cast<float4*>(outrow) = o0;
    *reinterpret_cast<float4*>(outrow + 4) = o1;
}

// ---------------- fused pooling + output head ----------------
// Block g: pooled row (256) in smem, then 8 warps compute the 16 outputs.
__global__ void pool_out_kernel(const float* __restrict__ h, const void* __restrict__ batch,
                                int n, const float* __restrict__ W, const float* __restrict__ b,
                                float* __restrict__ out) {
    __shared__ int sRange[2];
    __shared__ float sPool[HID];
    __shared__ float sPart[8][NCLS];
    int g = blockIdx.x;
    int tid = threadIdx.x;
    if (tid < 2) {
        int target = g + tid;
        int is64 = g_is64;
        int lo = 0, hi = n;
        while (lo < hi) {
            int mid = (lo + hi) >> 1;
            if (get_idx(batch, mid, is64) < target) lo = mid + 1; else hi = mid;
        }
        sRange[tid] = lo;
    }
    __syncthreads();
    int beg = sRange[0];
    int end = sRange[1];
    float sum = 0.0f;
    for (int i = beg; i < end; i++) sum += h[(size_t)i * HID + tid];
    sPool[tid] = sum / fmaxf((float)(end - beg), 1.0f);
    __syncthreads();

    // 256 threads -> thread t computes partial for class c = t & 15 over k-chunk (t>>4)*16..+16
    {
        int c = tid & 15;
        int k0 = (tid >> 4) * 16;
        float p = 0.0f;
#pragma unroll
        for (int k = 0; k < 16; k++) p += sPool[k0 + k] * W[(k0 + k) * NCLS + c];
        // reduce 16 chunk-partials per class: first half adds into sPart via two stages
        // stage 1: chunks 0..7 and 8..15 -> use shuffle-free smem reduction
        __shared__ float sAll[16][NCLS];
        sAll[tid >> 4][c] = p;
        __syncthreads();
        if (tid < NCLS) {
            float s = b[tid];
#pragma unroll
            for (int q = 0; q < 16; q++) s += sAll[q][tid];
            out[g * NCLS + tid] = s;
        }
    }
}

// ---------------- launch ----------------
extern "C" void kernel_launch(void* const* d_in, const int* in_sizes, int n_in,
                              void* d_out, int out_size) {
    const float* x     = (const float*)d_in[0];
    const void*  ei    = d_in[1];
    const void*  batch = d_in[2];
    const float* W_in  = (const float*)d_in[3];
    const float* b_in  = (const float*)d_in[4];
    const float* W1    = (const float*)d_in[5];
    const float* b1    = (const float*)d_in[6];
    const float* W2    = (const float*)d_in[7];
    const float* b2    = (const float*)d_in[8];
    const float* W_out = (const float*)d_in[9];
    const float* b_out = (const float*)d_in[10];

    const int N = in_sizes[0] / INDIM;
    const int E = in_sizes[1] / 2;

    float *bufA, *dinv;
    __nv_bfloat16* bufH;
    int *indeg, *row_ptr, *cursor, *csr_src, *localscan;
    cudaGetSymbolAddress((void**)&bufA, g_bufA);
    cudaGetSymbolAddress((void**)&bufH, g_bufH);
    cudaGetSymbolAddress((void**)&dinv, g_dinv);
    cudaGetSymbolAddress((void**)&indeg, g_indeg);
    cudaGetSymbolAddress((void**)&row_ptr, g_row_ptr);
    cudaGetSymbolAddress((void**)&cursor, g_cursor);
    cudaGetSymbolAddress((void**)&csr_src, g_csr_src);
    cudaGetSymbolAddress((void**)&localscan, g_localscan);

    detect_dtype_kernel<<<1, 256>>>((const int*)ei, 4096);

    cudaMemsetAsync(indeg, 0, N * sizeof(int), 0);
    hist_dst_kernel<<<(E + 255) / 256, 256>>>(ei, E, indeg);

    const int nb = (N + 1023) / 1024;
    scan_local_kernel<<<nb, 1024>>>(indeg, localscan, N);
    scan_finalize_kernel<<<(N + 255) / 256, 256>>>(indeg, localscan, row_ptr, cursor, dinv, N);
    fill_csr_kernel<<<(E + 255) / 256, 256>>>(ei, E, cursor, csr_src);

    const int GEMM_GRID = 296;   // 148 SMs x 2 CTAs

    tf32gemm_kernel<<<GEMM_GRID, 256>>>(x, W_in, bufA, nullptr, N, INDIM, b_in, nullptr);

    tf32gemm_kernel<<<GEMM_GRID, 256>>>(bufA, W1, nullptr, bufH, N, HID, nullptr, dinv);
    gather_kernel<<<(N * 32 + 255) / 256, 256>>>(bufH, bufA, row_ptr, csr_src, dinv, b1, N);

    tf32gemm_kernel<<<GEMM_GRID, 256>>>(bufA, W2, nullptr, bufH, N, HID, nullptr, dinv);
    gather_kernel<<<(N * 32 + 255) / 256, 256>>>(bufH, bufA, row_ptr, csr_src, dinv, b2, N);

    pool_out_kernel<<<NGRAPH, HID>>>(bufA, batch, N, W_out, b_out, (float*)d_out);
}

// round 10
// speedup vs baseline: 1.6347x; 1.0592x over previous
#include <cuda_runtime.h>
#include <cuda_bf16.h>
#include <cstdint>

// Problem constants
#define NNODES 50000
#define NEDGES 800000
#define INDIM  128
#define HID    256
#define NGRAPH 128
#define NCLS   16

// ---------------- device scratch ----------------
__device__ float          g_bufA[NNODES * HID];
__device__ __nv_bfloat16  g_bufH[NNODES * HID];
__device__ float g_dinv[NNODES];
__device__ int   g_indeg[NNODES];
__device__ int   g_row_ptr[NNODES + 1];
__device__ int   g_cursor[NNODES];
__device__ int   g_csr_src[NEDGES];
__device__ int   g_localscan[NNODES];
__device__ int   g_blocksum[64];
__device__ int   g_is64;

__device__ __forceinline__ int get_idx(const void* p, int i, int is64) {
    if (is64) return (int)((const long long*)p)[i];
    return ((const int*)p)[i];
}

__device__ __forceinline__ void cp_async16(uint32_t saddr, const void* gptr) {
    asm volatile("cp.async.cg.shared.global [%0], [%1], 16;" :: "r"(saddr), "l"(gptr));
}
__device__ __forceinline__ void cp_commit() {
    asm volatile("cp.async.commit_group;");
}
template <int N>
__device__ __forceinline__ void cp_wait() {
    asm volatile("cp.async.wait_group %0;" :: "n"(N));
}

__device__ __forceinline__ uint32_t rna_tf32(uint32_t bits) {
    uint32_t u;
    asm("cvt.rna.tf32.f32 %0, %1;" : "=r"(u) : "f"(__uint_as_float(bits)));
    return u;
}

// acc[j] += scale * bf16row[j]
__device__ __forceinline__ void fma_bf16x8(float* acc, uint4 u, float scale) {
    const __nv_bfloat162* p = reinterpret_cast<const __nv_bfloat162*>(&u);
#pragma unroll
    for (int q = 0; q < 4; q++) {
        float2 f = __bfloat1622float2(p[q]);
        acc[2 * q]     = fmaf(f.x, scale, acc[2 * q]);
        acc[2 * q + 1] = fmaf(f.y, scale, acc[2 * q + 1]);
    }
}

// ---------------- dtype detection ----------------
__global__ void detect_dtype_kernel(const int* __restrict__ w, int nOddSamples) {
    __shared__ int found;
    if (threadIdx.x == 0) found = 0;
    __syncthreads();
    for (int i = threadIdx.x; i < nOddSamples; i += blockDim.x) {
        if (w[2 * i + 1] != 0) found = 1;
    }
    __syncthreads();
    if (threadIdx.x == 0) g_is64 = found ? 0 : 1;
}

// ---------------- preprocessing ----------------
__global__ void hist_dst_kernel(const void* __restrict__ ei, int E, int* __restrict__ indeg) {
    int e = blockIdx.x * blockDim.x + threadIdx.x;
    if (e < E) {
        int d = get_idx(ei, E + e, g_is64);
        atomicAdd(&indeg[d], 1);
    }
}

__global__ void scan_local_kernel(const int* __restrict__ counts, int* __restrict__ localscan, int n) {
    __shared__ int s[1024];
    int tid = threadIdx.x;
    int i = blockIdx.x * 1024 + tid;
    int v = (i < n) ? counts[i] : 0;
    s[tid] = v;
    __syncthreads();
    for (int off = 1; off < 1024; off <<= 1) {
        int t = (tid >= off) ? s[tid - off] : 0;
        __syncthreads();
        s[tid] += t;
        __syncthreads();
    }
    if (i < n) localscan[i] = s[tid];
    if (tid == 1023) g_blocksum[blockIdx.x] = s[1023];
}

__global__ void scan_finalize_kernel(const int* __restrict__ counts, const int* __restrict__ localscan,
                                     int* __restrict__ row_ptr, int* __restrict__ cursor,
                                     float* __restrict__ dinv, int n) {
    __shared__ int sOff;
    int bucket = blockIdx.x >> 2;
    if (threadIdx.x == 0) {
        int off = 0;
        for (int j = 0; j < bucket; j++) off += g_blocksum[j];
        sOff = off;
    }
    __syncthreads();
    int i = blockIdx.x * blockDim.x + threadIdx.x;
    if (i < n) {
        int cnt = counts[i];
        int incl = localscan[i] + sOff;
        row_ptr[i + 1] = incl;
        cursor[i] = incl - cnt;
        dinv[i] = rsqrtf((float)cnt + 1.0f);
        if (i == 0) row_ptr[0] = 0;
    }
}

__global__ void fill_csr_kernel(const void* __restrict__ ei, int E,
                                int* __restrict__ cursor, int* __restrict__ csr_src) {
    int e = blockIdx.x * blockDim.x + threadIdx.x;
    if (e < E) {
        int is64 = g_is64;
        int d = get_idx(ei, E + e, is64);
        int s = get_idx(ei, e, is64);
        int pos = atomicAdd(&cursor[d], 1);
        csr_src[pos] = s;
    }
}

// ---------------- TF32 GEMM: persistent CTAs + cp.async double buffering ----------------
// No scale path anymore: fp32 out (+bias) or raw bf16 out.
#define BM 128
#define BN 128
#define BK 16
#define AS_K 20
#define BS_N 136

__global__ __launch_bounds__(256, 2) void tf32gemm_kernel(
    const float* __restrict__ A, const float* __restrict__ B,
    float* __restrict__ C, __nv_bfloat16* __restrict__ Cbf,
    int M, int K, const float* __restrict__ bias) {
    __shared__ uint32_t As[2][BM * AS_K];
    __shared__ uint32_t Bs[2][BK * BS_N];

    const int tid = threadIdx.x;
    const int wid = tid >> 5;
    const int lane = tid & 31;
    const int warpM = wid & 3;
    const int warpN = wid >> 2;
    const int g = lane >> 2;
    const int t4 = lane & 3;
    const int mB = warpM * 32;
    const int nB = warpN * 64;

    const int aRow0 = tid >> 2;
    const int aRow1 = 64 + (tid >> 2);
    const int aC = (tid & 3) * 4;
    const int bRow0 = tid >> 5;
    const int bRow1 = 8 + (tid >> 5);
    const int bCol = (tid & 31) * 4;

    const uint32_t asBytes = BM * AS_K * 4;
    const uint32_t bsBytes = BK * BS_N * 4;
    const uint32_t sa0 = (uint32_t)__cvta_generic_to_shared(&As[0][aRow0 * AS_K + aC]);
    const uint32_t sa1 = (uint32_t)__cvta_generic_to_shared(&As[0][aRow1 * AS_K + aC]);
    const uint32_t sb0 = (uint32_t)__cvta_generic_to_shared(&Bs[0][bRow0 * BS_N + bCol]);
    const uint32_t sb1 = (uint32_t)__cvta_generic_to_shared(&Bs[0][bRow1 * BS_N + bCol]);

    const int nTiles = K / BK;
    const int numRowTiles = (M + BM - 1) / BM;
    const int numTiles = numRowTiles * (HID / BN);

    for (int bt = blockIdx.x; bt < numTiles; bt += gridDim.x) {
        const int rowBase = (bt >> 1) * BM;
        const int colBase = (bt & 1) * BN;

        int gr0 = rowBase + aRow0; gr0 = gr0 < M ? gr0 : M - 1;
        int gr1 = rowBase + aRow1; gr1 = gr1 < M ? gr1 : M - 1;
        const float* aPtr0 = A + (size_t)gr0 * K + aC;
        const float* aPtr1 = A + (size_t)gr1 * K + aC;
        const float* bPtr0 = B + (size_t)bRow0 * HID + colBase + bCol;
        const float* bPtr1 = B + (size_t)bRow1 * HID + colBase + bCol;

        float acc[2][8][4];
#pragma unroll
        for (int mt = 0; mt < 2; mt++)
#pragma unroll
            for (int nt = 0; nt < 8; nt++)
#pragma unroll
                for (int c = 0; c < 4; c++) acc[mt][nt][c] = 0.0f;

        cp_async16(sa0, aPtr0);
        cp_async16(sa1, aPtr1);
        cp_async16(sb0, bPtr0);
        cp_async16(sb1, bPtr1);
        cp_commit();
        if (nTiles > 1) {
            cp_async16(sa0 + asBytes, aPtr0 + BK);
            cp_async16(sa1 + asBytes, aPtr1 + BK);
            cp_async16(sb0 + bsBytes, bPtr0 + (size_t)BK * HID);
            cp_async16(sb1 + bsBytes, bPtr1 + (size_t)BK * HID);
            cp_commit();
        }

        for (int t = 0; t < nTiles; t++) {
            if (t + 1 < nTiles) cp_wait<1>(); else cp_wait<0>();
            __syncthreads();

            const int st = t & 1;
            const uint32_t* AsS = As[st];
            const uint32_t* BsS = Bs[st];

#pragma unroll
            for (int ks = 0; ks < BK; ks += 8) {
                uint32_t af[2][4];
#pragma unroll
                for (int mt = 0; mt < 2; mt++) {
                    int m0 = mB + mt * 16 + g;
                    af[mt][0] = rna_tf32(AsS[m0 * AS_K + ks + t4]);
                    af[mt][1] = rna_tf32(AsS[(m0 + 8) * AS_K + ks + t4]);
                    af[mt][2] = rna_tf32(AsS[m0 * AS_K + ks + t4 + 4]);
                    af[mt][3] = rna_tf32(AsS[(m0 + 8) * AS_K + ks + t4 + 4]);
                }
                uint32_t bf[8][2];
#pragma unroll
                for (int nt = 0; nt < 8; nt++) {
                    int n0 = nB + nt * 8 + g;
                    bf[nt][0] = rna_tf32(BsS[(ks + t4) * BS_N + n0]);
                    bf[nt][1] = rna_tf32(BsS[(ks + t4 + 4) * BS_N + n0]);
                }
#pragma unroll
                for (int mt = 0; mt < 2; mt++)
#pragma unroll
                    for (int nt = 0; nt < 8; nt++) {
                        asm volatile(
                            "mma.sync.aligned.m16n8k8.row.col.f32.tf32.tf32.f32 "
                            "{%0,%1,%2,%3}, {%4,%5,%6,%7}, {%8,%9}, {%0,%1,%2,%3};"
                            : "+f"(acc[mt][nt][0]), "+f"(acc[mt][nt][1]),
                              "+f"(acc[mt][nt][2]), "+f"(acc[mt][nt][3])
                            : "r"(af[mt][0]), "r"(af[mt][1]), "r"(af[mt][2]), "r"(af[mt][3]),
                              "r"(bf[nt][0]), "r"(bf[nt][1]));
                    }
            }
            __syncthreads();

            if (t + 2 < nTiles) {
                int k0 = (t + 2) * BK;
                uint32_t off = st ? asBytes : 0;
                uint32_t offB = st ? bsBytes : 0;
                cp_async16(sa0 + off, aPtr0 + k0);
                cp_async16(sa1 + off, aPtr1 + k0);
                cp_async16(sb0 + offB, bPtr0 + (size_t)k0 * HID);
                cp_async16(sb1 + offB, bPtr1 + (size_t)k0 * HID);
                cp_commit();
            }
        }

        // epilogue
#pragma unroll
        for (int mt = 0; mt < 2; mt++) {
            int r0 = rowBase + mB + mt * 16 + g;
            int r1 = r0 + 8;
#pragma unroll
            for (int nt = 0; nt < 8; nt++) {
                int c = colBase + nB + nt * 8 + t4 * 2;
                float bx = 0.f, by = 0.f;
                if (bias) { bx = bias[c]; by = bias[c + 1]; }
                float v0x = acc[mt][nt][0] + bx;
                float v0y = acc[mt][nt][1] + by;
                float v1x = acc[mt][nt][2] + bx;
                float v1y = acc[mt][nt][3] + by;
                if (Cbf) {
                    if (r0 < M) {
                        __nv_bfloat162 p = __floats2bfloat162_rn(v0x, v0y);
                        *reinterpret_cast<__nv_bfloat162*>(&Cbf[(size_t)r0 * HID + c]) = p;
                    }
                    if (r1 < M) {
                        __nv_bfloat162 p = __floats2bfloat162_rn(v1x, v1y);
                        *reinterpret_cast<__nv_bfloat162*>(&Cbf[(size_t)r1 * HID + c]) = p;
                    }
                } else {
                    if (r0 < M) {
                        float2 v = make_float2(v0x, v0y);
                        *reinterpret_cast<float2*>(&C[(size_t)r0 * HID + c]) = v;
                    }
                    if (r1 < M) {
                        float2 v = make_float2(v1x, v1y);
                        *reinterpret_cast<float2*>(&C[(size_t)r1 * HID + c]) = v;
                    }
                }
            }
        }
        __syncthreads();
    }
}

// ---------------- gather: out[d] = relu(dinv[d]*(sum_src dinv[s]*h'[s] + dinv[d]*h'[d]) + b) ----------------
__global__ void gather_kernel(const __nv_bfloat16* __restrict__ hp, float* __restrict__ out,
                              const int* __restrict__ row_ptr, const int* __restrict__ csr_src,
                              const float* __restrict__ dinv, const float* __restrict__ bias, int n) {
    int warp = (blockIdx.x * blockDim.x + threadIdx.x) >> 5;
    int lane = threadIdx.x & 31;
    if (warp >= n) return;
    int beg = row_ptr[warp];
    int end = row_ptr[warp + 1];
    const int colOff = lane * 8;

    float a0[8], a1[8];
#pragma unroll
    for (int j = 0; j < 8; j++) { a0[j] = 0.f; a1[j] = 0.f; }

    int e = beg;
    for (; e + 8 <= end; e += 8) {
        int s[8];
#pragma unroll
        for (int q = 0; q < 8; q++) s[q] = csr_src[e + q];
        uint4 u[8];
        float dv[8];
#pragma unroll
        for (int q = 0; q < 8; q++) {
            u[q] = __ldg(reinterpret_cast<const uint4*>(hp + (size_t)s[q] * HID + colOff));
            dv[q] = __ldg(&dinv[s[q]]);
        }
#pragma unroll
        for (int q = 0; q < 8; q++) fma_bf16x8((q & 1) ? a1 : a0, u[q], dv[q]);
    }
    if (e + 4 <= end) {
        int s[4];
#pragma unroll
        for (int q = 0; q < 4; q++) s[q] = csr_src[e + q];
        uint4 u[4];
        float dv[4];
#pragma unroll
        for (int q = 0; q < 4; q++) {
            u[q] = __ldg(reinterpret_cast<const uint4*>(hp + (size_t)s[q] * HID + colOff));
            dv[q] = __ldg(&dinv[s[q]]);
        }
#pragma unroll
        for (int q = 0; q < 4; q++) fma_bf16x8((q & 1) ? a1 : a0, u[q], dv[q]);
        e += 4;
    }
    for (; e < end; e++) {
        int s = csr_src[e];
        uint4 u = __ldg(reinterpret_cast<const uint4*>(hp + (size_t)s * HID + colOff));
        float dv = __ldg(&dinv[s]);
        fma_bf16x8(a0, u, dv);
    }

    float dvd = dinv[warp];
    // self contribution: dinv[d] * h'[d]
    {
        uint4 u = *reinterpret_cast<const uint4*>(hp + (size_t)warp * HID + colOff);
        fma_bf16x8(a1, u, dvd);
    }

    float4 b0 = *reinterpret_cast<const float4*>(bias + colOff);
    float4 b1 = *reinterpret_cast<const float4*>(bias + colOff + 4);
    float4 o0, o1;
    o0.x = fmaxf(dvd * (a0[0] + a1[0]) + b0.x, 0.f);
    o0.y = fmaxf(dvd * (a0[1] + a1[1]) + b0.y, 0.f);
    o0.z = fmaxf(dvd * (a0[2] + a1[2]) + b0.z, 0.f);
    o0.w = fmaxf(dvd * (a0[3] + a1[3]) + b0.w, 0.f);
    o1.x = fmaxf(dvd * (a0[4] + a1[4]) + b1.x, 0.f);
    o1.y = fmaxf(dvd * (a0[5] + a1[5]) + b1.y, 0.f);
    o1.z = fmaxf(dvd * (a0[6] + a1[6]) + b1.z, 0.f);
    o1.w = fmaxf(dvd * (a0[7] + a1[7]) + b1.w, 0.f);

    float* outrow = out + (size_t)warp * HID + colOff;
    *reinterpret_cast<float4*>(outrow) = o0;
    *reinterpret_cast<float4*>(outrow + 4) = o1;
}

// ---------------- fused pooling + output head ----------------
__global__ void pool_out_kernel(const float* __restrict__ h, const void* __restrict__ batch,
                                int n, const float* __restrict__ W, const float* __restrict__ b,
                                float* __restrict__ out) {
    __shared__ int sRange[2];
    __shared__ float sPool[HID];
    int g = blockIdx.x;
    int tid = threadIdx.x;
    if (tid < 2) {
        int target = g + tid;
        int is64 = g_is64;
        int lo = 0, hi = n;
        while (lo < hi) {
            int mid = (lo + hi) >> 1;
            if (get_idx(batch, mid, is64) < target) lo = mid + 1; else hi = mid;
        }
        sRange[tid] = lo;
    }
    __syncthreads();
    int beg = sRange[0];
    int end = sRange[1];
    float sum = 0.0f;
    for (int i = beg; i < end; i++) sum += h[(size_t)i * HID + tid];
    sPool[tid] = sum / fmaxf((float)(end - beg), 1.0f);
    __syncthreads();

    {
        int c = tid & 15;
        int k0 = (tid >> 4) * 16;
        float p = 0.0f;
#pragma unroll
        for (int k = 0; k < 16; k++) p += sPool[k0 + k] * W[(k0 + k) * NCLS + c];
        __shared__ float sAll[16][NCLS];
        sAll[tid >> 4][c] = p;
        __syncthreads();
        if (tid < NCLS) {
            float s = b[tid];
#pragma unroll
            for (int q = 0; q < 16; q++) s += sAll[q][tid];
            out[g * NCLS + tid] = s;
        }
    }
}

// ---------------- launch ----------------
extern "C" void kernel_launch(void* const* d_in, const int* in_sizes, int n_in,
                              void* d_out, int out_size) {
    const float* x     = (const float*)d_in[0];
    const void*  ei    = d_in[1];
    const void*  batch = d_in[2];
    const float* W_in  = (const float*)d_in[3];
    const float* b_in  = (const float*)d_in[4];
    const float* W1    = (const float*)d_in[5];
    const float* b1    = (const float*)d_in[6];
    const float* W2    = (const float*)d_in[7];
    const float* b2    = (const float*)d_in[8];
    const float* W_out = (const float*)d_in[9];
    const float* b_out = (const float*)d_in[10];

    const int N = in_sizes[0] / INDIM;
    const int E = in_sizes[1] / 2;

    float *bufA, *dinv;
    __nv_bfloat16* bufH;
    int *indeg, *row_ptr, *cursor, *csr_src, *localscan;
    cudaGetSymbolAddress((void**)&bufA, g_bufA);
    cudaGetSymbolAddress((void**)&bufH, g_bufH);
    cudaGetSymbolAddress((void**)&dinv, g_dinv);
    cudaGetSymbolAddress((void**)&indeg, g_indeg);
    cudaGetSymbolAddress((void**)&row_ptr, g_row_ptr);
    cudaGetSymbolAddress((void**)&cursor, g_cursor);
    cudaGetSymbolAddress((void**)&csr_src, g_csr_src);
    cudaGetSymbolAddress((void**)&localscan, g_localscan);

    // lazily-created side stream + fork/join events (host resources, created once)
    static cudaStream_t sSide = nullptr;
    static cudaEvent_t evFork = nullptr, evJoin = nullptr;
    if (sSide == nullptr) {
        cudaStreamCreateWithFlags(&sSide, cudaStreamNonBlocking);
        cudaEventCreateWithFlags(&evFork, cudaEventDisableTiming);
        cudaEventCreateWithFlags(&evJoin, cudaEventDisableTiming);
    }

    const int GEMM_GRID = 296;   // 148 SMs x 2 CTAs

    // ---- fork: preprocessing on side stream, GEMM1+GEMM2 on main stream ----
    cudaEventRecord(evFork, 0);
    cudaStreamWaitEvent(sSide, evFork, 0);

    detect_dtype_kernel<<<1, 256, 0, sSide>>>((const int*)ei, 4096);
    cudaMemsetAsync(indeg, 0, N * sizeof(int), sSide);
    hist_dst_kernel<<<(E + 255) / 256, 256, 0, sSide>>>(ei, E, indeg);
    const int nb = (N + 1023) / 1024;
    scan_local_kernel<<<nb, 1024, 0, sSide>>>(indeg, localscan, N);
    scan_finalize_kernel<<<(N + 255) / 256, 256, 0, sSide>>>(indeg, localscan, row_ptr, cursor, dinv, N);
    fill_csr_kernel<<<(E + 255) / 256, 256, 0, sSide>>>(ei, E, cursor, csr_src);
    cudaEventRecord(evJoin, sSide);

    // main stream: GEMM1 (x@W_in + b_in -> fp32 bufA), GEMM2 (bufA@W1 -> raw bf16 bufH)
    tf32gemm_kernel<<<GEMM_GRID, 256>>>(x, W_in, bufA, nullptr, N, INDIM, b_in);
    tf32gemm_kernel<<<GEMM_GRID, 256>>>(bufA, W1, nullptr, bufH, N, HID, nullptr);

    // ---- join ----
    cudaStreamWaitEvent(0, evJoin, 0);

    gather_kernel<<<(N * 32 + 255) / 256, 256>>>(bufH, bufA, row_ptr, csr_src, dinv, b1, N);

    tf32gemm_kernel<<<GEMM_GRID, 256>>>(bufA, W2, nullptr, bufH, N, HID, nullptr);
    gather_kernel<<<(N * 32 + 255) / 256, 256>>>(bufH, bufA, row_ptr, csr_src, dinv, b2, N);

    pool_out_kernel<<<NGRAPH, HID>>>(bufA, batch, N, W_out, b_out, (float*)d_out);
}

// round 11
// speedup vs baseline: 1.8950x; 1.1592x over previous
#include <cuda_runtime.h>
#include <cuda_bf16.h>
#include <cstdint>

// Problem constants
#define NNODES 50000
#define NEDGES 800000
#define INDIM  128
#define HID    256
#define NGRAPH 128
#define NCLS   16

// ---------------- device scratch ----------------
__device__ float          g_bufA[NNODES * HID];
__device__ __nv_bfloat16  g_bufH[NNODES * HID];
__device__ float g_Wcomb[INDIM * HID];
__device__ float g_bcomb[HID];
__device__ float g_dinv[NNODES];
__device__ int   g_indeg[NNODES];
__device__ int   g_row_ptr[NNODES + 1];
__device__ int   g_cursor[NNODES];
__device__ int   g_csr_src[NEDGES];
__device__ int   g_localscan[NNODES];
__device__ int   g_blocksum[64];
__device__ int   g_is64;

__device__ __forceinline__ int get_idx(const void* p, int i, int is64) {
    if (is64) return (int)((const long long*)p)[i];
    return ((const int*)p)[i];
}

__device__ __forceinline__ void cp_async16(uint32_t saddr, const void* gptr) {
    asm volatile("cp.async.cg.shared.global [%0], [%1], 16;" :: "r"(saddr), "l"(gptr));
}
__device__ __forceinline__ void cp_commit() {
    asm volatile("cp.async.commit_group;");
}
template <int N>
__device__ __forceinline__ void cp_wait() {
    asm volatile("cp.async.wait_group %0;" :: "n"(N));
}

__device__ __forceinline__ uint32_t rna_tf32(uint32_t bits) {
    uint32_t u;
    asm("cvt.rna.tf32.f32 %0, %1;" : "=r"(u) : "f"(__uint_as_float(bits)));
    return u;
}

// acc[j] += scale * bf16row[j]
__device__ __forceinline__ void fma_bf16x8(float* acc, uint4 u, float scale) {
    const __nv_bfloat162* p = reinterpret_cast<const __nv_bfloat162*>(&u);
#pragma unroll
    for (int q = 0; q < 4; q++) {
        float2 f = __bfloat1622float2(p[q]);
        acc[2 * q]     = fmaf(f.x, scale, acc[2 * q]);
        acc[2 * q + 1] = fmaf(f.y, scale, acc[2 * q + 1]);
    }
}

// ---------------- dtype detection ----------------
__global__ void detect_dtype_kernel(const int* __restrict__ w, int nOddSamples) {
    __shared__ int found;
    if (threadIdx.x == 0) found = 0;
    __syncthreads();
    for (int i = threadIdx.x; i < nOddSamples; i += blockDim.x) {
        if (w[2 * i + 1] != 0) found = 1;
    }
    __syncthreads();
    if (threadIdx.x == 0) g_is64 = found ? 0 : 1;
}

// ---------------- weight folding: Wcomb = W_in @ W1, bcomb = b_in @ W1 (fp32 exact path) ----------------
__global__ void weight_combine_kernel(const float* __restrict__ Win, const float* __restrict__ bin,
                                      const float* __restrict__ W1,
                                      float* __restrict__ Wcomb, float* __restrict__ bcomb) {
    __shared__ float sRow[HID];
    int i = blockIdx.x;   // 0..INDIM: row of W_in, or INDIM -> b_in
    int j = threadIdx.x;  // 0..HID-1
    const float* row = (i < INDIM) ? (Win + (size_t)i * HID) : bin;
    // W_in rows have only INDIM? no: W_in is [INDIM, HID]? careful: W_in[IN_DIM][HID] row length HID? No!
    // W_in is [IN_DIM=128 rows, HID=256 cols]... but the product W_in@W1 sums over HID? NO:
    // h = x@W_in: x[N,128] @ W_in[128,256]. Then h@W1: [N,256]@[256,256].
    // So Wcomb = W_in@W1: [128,256]@[256,256] -> [128,256]; row i of W_in has HID=256 entries. Correct.
    sRow[j] = row[j];
    __syncthreads();
    float s = 0.f;
    for (int k = 0; k < HID; k++) s = fmaf(sRow[k], W1[(size_t)k * HID + j], s);
    if (i < INDIM) Wcomb[(size_t)i * HID + j] = s;
    else bcomb[j] = s;
}

// ---------------- preprocessing ----------------
__global__ void hist_dst_kernel(const void* __restrict__ ei, int E, int* __restrict__ indeg) {
    int e = blockIdx.x * blockDim.x + threadIdx.x;
    if (e < E) {
        int d = get_idx(ei, E + e, g_is64);
        atomicAdd(&indeg[d], 1);
    }
}

__global__ void scan_local_kernel(const int* __restrict__ counts, int* __restrict__ localscan, int n) {
    __shared__ int s[1024];
    int tid = threadIdx.x;
    int i = blockIdx.x * 1024 + tid;
    int v = (i < n) ? counts[i] : 0;
    s[tid] = v;
    __syncthreads();
    for (int off = 1; off < 1024; off <<= 1) {
        int t = (tid >= off) ? s[tid - off] : 0;
        __syncthreads();
        s[tid] += t;
        __syncthreads();
    }
    if (i < n) localscan[i] = s[tid];
    if (tid == 1023) g_blocksum[blockIdx.x] = s[1023];
}

__global__ void scan_finalize_kernel(const int* __restrict__ counts, const int* __restrict__ localscan,
                                     int* __restrict__ row_ptr, int* __restrict__ cursor,
                                     float* __restrict__ dinv, int n) {
    __shared__ int sOff;
    int bucket = blockIdx.x >> 2;
    if (threadIdx.x == 0) {
        int off = 0;
        for (int j = 0; j < bucket; j++) off += g_blocksum[j];
        sOff = off;
    }
    __syncthreads();
    int i = blockIdx.x * blockDim.x + threadIdx.x;
    if (i < n) {
        int cnt = counts[i];
        int incl = localscan[i] + sOff;
        row_ptr[i + 1] = incl;
        cursor[i] = incl - cnt;
        dinv[i] = rsqrtf((float)cnt + 1.0f);
        if (i == 0) row_ptr[0] = 0;
    }
}

__global__ void fill_csr_kernel(const void* __restrict__ ei, int E,
                                int* __restrict__ cursor, int* __restrict__ csr_src) {
    int e = blockIdx.x * blockDim.x + threadIdx.x;
    if (e < E) {
        int is64 = g_is64;
        int d = get_idx(ei, E + e, is64);
        int s = get_idx(ei, e, is64);
        int pos = atomicAdd(&cursor[d], 1);
        csr_src[pos] = s;
    }
}

// ---------------- TF32 GEMM: persistent CTAs + cp.async double buffering ----------------
#define BM 128
#define BN 128
#define BK 16
#define AS_K 20
#define BS_N 136

__global__ __launch_bounds__(256, 2) void tf32gemm_kernel(
    const float* __restrict__ A, const float* __restrict__ B,
    float* __restrict__ C, __nv_bfloat16* __restrict__ Cbf,
    int M, int K, const float* __restrict__ bias) {
    __shared__ uint32_t As[2][BM * AS_K];
    __shared__ uint32_t Bs[2][BK * BS_N];

    const int tid = threadIdx.x;
    const int wid = tid >> 5;
    const int lane = tid & 31;
    const int warpM = wid & 3;
    const int warpN = wid >> 2;
    const int g = lane >> 2;
    const int t4 = lane & 3;
    const int mB = warpM * 32;
    const int nB = warpN * 64;

    const int aRow0 = tid >> 2;
    const int aRow1 = 64 + (tid >> 2);
    const int aC = (tid & 3) * 4;
    const int bRow0 = tid >> 5;
    const int bRow1 = 8 + (tid >> 5);
    const int bCol = (tid & 31) * 4;

    const uint32_t asBytes = BM * AS_K * 4;
    const uint32_t bsBytes = BK * BS_N * 4;
    const uint32_t sa0 = (uint32_t)__cvta_generic_to_shared(&As[0][aRow0 * AS_K + aC]);
    const uint32_t sa1 = (uint32_t)__cvta_generic_to_shared(&As[0][aRow1 * AS_K + aC]);
    const uint32_t sb0 = (uint32_t)__cvta_generic_to_shared(&Bs[0][bRow0 * BS_N + bCol]);
    const uint32_t sb1 = (uint32_t)__cvta_generic_to_shared(&Bs[0][bRow1 * BS_N + bCol]);

    const int nTiles = K / BK;
    const int numRowTiles = (M + BM - 1) / BM;
    const int numTiles = numRowTiles * (HID / BN);

    for (int bt = blockIdx.x; bt < numTiles; bt += gridDim.x) {
        const int rowBase = (bt >> 1) * BM;
        const int colBase = (bt & 1) * BN;

        int gr0 = rowBase + aRow0; gr0 = gr0 < M ? gr0 : M - 1;
        int gr1 = rowBase + aRow1; gr1 = gr1 < M ? gr1 : M - 1;
        const float* aPtr0 = A + (size_t)gr0 * K + aC;
        const float* aPtr1 = A + (size_t)gr1 * K + aC;
        const float* bPtr0 = B + (size_t)bRow0 * HID + colBase + bCol;
        const float* bPtr1 = B + (size_t)bRow1 * HID + colBase + bCol;

        float acc[2][8][4];
#pragma unroll
        for (int mt = 0; mt < 2; mt++)
#pragma unroll
            for (int nt = 0; nt < 8; nt++)
#pragma unroll
                for (int c = 0; c < 4; c++) acc[mt][nt][c] = 0.0f;

        cp_async16(sa0, aPtr0);
        cp_async16(sa1, aPtr1);
        cp_async16(sb0, bPtr0);
        cp_async16(sb1, bPtr1);
        cp_commit();
        if (nTiles > 1) {
            cp_async16(sa0 + asBytes, aPtr0 + BK);
            cp_async16(sa1 + asBytes, aPtr1 + BK);
            cp_async16(sb0 + bsBytes, bPtr0 + (size_t)BK * HID);
            cp_async16(sb1 + bsBytes, bPtr1 + (size_t)BK * HID);
            cp_commit();
        }

        for (int t = 0; t < nTiles; t++) {
            if (t + 1 < nTiles) cp_wait<1>(); else cp_wait<0>();
            __syncthreads();

            const int st = t & 1;
            const uint32_t* AsS = As[st];
            const uint32_t* BsS = Bs[st];

#pragma unroll
            for (int ks = 0; ks < BK; ks += 8) {
                uint32_t af[2][4];
#pragma unroll
                for (int mt = 0; mt < 2; mt++) {
                    int m0 = mB + mt * 16 + g;
                    af[mt][0] = rna_tf32(AsS[m0 * AS_K + ks + t4]);
                    af[mt][1] = rna_tf32(AsS[(m0 + 8) * AS_K + ks + t4]);
                    af[mt][2] = rna_tf32(AsS[m0 * AS_K + ks + t4 + 4]);
                    af[mt][3] = rna_tf32(AsS[(m0 + 8) * AS_K + ks + t4 + 4]);
                }
                uint32_t bf[8][2];
#pragma unroll
                for (int nt = 0; nt < 8; nt++) {
                    int n0 = nB + nt * 8 + g;
                    bf[nt][0] = rna_tf32(BsS[(ks + t4) * BS_N + n0]);
                    bf[nt][1] = rna_tf32(BsS[(ks + t4 + 4) * BS_N + n0]);
                }
#pragma unroll
                for (int mt = 0; mt < 2; mt++)
#pragma unroll
                    for (int nt = 0; nt < 8; nt++) {
                        asm volatile(
                            "mma.sync.aligned.m16n8k8.row.col.f32.tf32.tf32.f32 "
                            "{%0,%1,%2,%3}, {%4,%5,%6,%7}, {%8,%9}, {%0,%1,%2,%3};"
                            : "+f"(acc[mt][nt][0]), "+f"(acc[mt][nt][1]),
                              "+f"(acc[mt][nt][2]), "+f"(acc[mt][nt][3])
                            : "r"(af[mt][0]), "r"(af[mt][1]), "r"(af[mt][2]), "r"(af[mt][3]),
                              "r"(bf[nt][0]), "r"(bf[nt][1]));
                    }
            }
            __syncthreads();

            if (t + 2 < nTiles) {
                int k0 = (t + 2) * BK;
                uint32_t off = st ? asBytes : 0;
                uint32_t offB = st ? bsBytes : 0;
                cp_async16(sa0 + off, aPtr0 + k0);
                cp_async16(sa1 + off, aPtr1 + k0);
                cp_async16(sb0 + offB, bPtr0 + (size_t)k0 * HID);
                cp_async16(sb1 + offB, bPtr1 + (size_t)k0 * HID);
                cp_commit();
            }
        }

        // epilogue
#pragma unroll
        for (int mt = 0; mt < 2; mt++) {
            int r0 = rowBase + mB + mt * 16 + g;
            int r1 = r0 + 8;
#pragma unroll
            for (int nt = 0; nt < 8; nt++) {
                int c = colBase + nB + nt * 8 + t4 * 2;
                float bx = 0.f, by = 0.f;
                if (bias) { bx = bias[c]; by = bias[c + 1]; }
                float v0x = acc[mt][nt][0] + bx;
                float v0y = acc[mt][nt][1] + by;
                float v1x = acc[mt][nt][2] + bx;
                float v1y = acc[mt][nt][3] + by;
                if (Cbf) {
                    if (r0 < M) {
                        __nv_bfloat162 p = __floats2bfloat162_rn(v0x, v0y);
                        *reinterpret_cast<__nv_bfloat162*>(&Cbf[(size_t)r0 * HID + c]) = p;
                    }
                    if (r1 < M) {
                        __nv_bfloat162 p = __floats2bfloat162_rn(v1x, v1y);
                        *reinterpret_cast<__nv_bfloat162*>(&Cbf[(size_t)r1 * HID + c]) = p;
                    }
                } else {
                    if (r0 < M) {
                        float2 v = make_float2(v0x, v0y);
                        *reinterpret_cast<float2*>(&C[(size_t)r0 * HID + c]) = v;
                    }
                    if (r1 < M) {
                        float2 v = make_float2(v1x, v1y);
                        *reinterpret_cast<float2*>(&C[(size_t)r1 * HID + c]) = v;
                    }
                }
            }
        }
        __syncthreads();
    }
}

// ---------------- gather: out[d] = relu(dinv[d]*(sum_src dinv[s]*h'[s] + dinv[d]*h'[d]) + b) ----------------
__global__ void gather_kernel(const __nv_bfloat16* __restrict__ hp, float* __restrict__ out,
                              const int* __restrict__ row_ptr, const int* __restrict__ csr_src,
                              const float* __restrict__ dinv, const float* __restrict__ bias, int n) {
    int warp = (blockIdx.x * blockDim.x + threadIdx.x) >> 5;
    int lane = threadIdx.x & 31;
    if (warp >= n) return;
    int beg = row_ptr[warp];
    int end = row_ptr[warp + 1];
    const int colOff = lane * 8;

    float a0[8], a1[8];
#pragma unroll
    for (int j = 0; j < 8; j++) { a0[j] = 0.f; a1[j] = 0.f; }

    int e = beg;
    for (; e + 8 <= end; e += 8) {
        int s[8];
#pragma unroll
        for (int q = 0; q < 8; q++) s[q] = csr_src[e + q];
        uint4 u[8];
        float dv[8];
#pragma unroll
        for (int q = 0; q < 8; q++) {
            u[q] = __ldg(reinterpret_cast<const uint4*>(hp + (size_t)s[q] * HID + colOff));
            dv[q] = __ldg(&dinv[s[q]]);
        }
#pragma unroll
        for (int q = 0; q < 8; q++) fma_bf16x8((q & 1) ? a1 : a0, u[q], dv[q]);
    }
    if (e + 4 <= end) {
        int s[4];
#pragma unroll
        for (int q = 0; q < 4; q++) s[q] = csr_src[e + q];
        uint4 u[4];
        float dv[4];
#pragma unroll
        for (int q = 0; q < 4; q++) {
            u[q] = __ldg(reinterpret_cast<const uint4*>(hp + (size_t)s[q] * HID + colOff));
            dv[q] = __ldg(&dinv[s[q]]);
        }
#pragma unroll
        for (int q = 0; q < 4; q++) fma_bf16x8((q & 1) ? a1 : a0, u[q], dv[q]);
        e += 4;
    }
    for (; e < end; e++) {
        int s = csr_src[e];
        uint4 u = __ldg(reinterpret_cast<const uint4*>(hp + (size_t)s * HID + colOff));
        float dv = __ldg(&dinv[s]);
        fma_bf16x8(a0, u, dv);
    }

    float dvd = dinv[warp];
    {
        uint4 u = *reinterpret_cast<const uint4*>(hp + (size_t)warp * HID + colOff);
        fma_bf16x8(a1, u, dvd);
    }

    float4 b0 = *reinterpret_cast<const float4*>(bias + colOff);
    float4 b1 = *reinterpret_cast<const float4*>(bias + colOff + 4);
    float4 o0, o1;
    o0.x = fmaxf(dvd * (a0[0] + a1[0]) + b0.x, 0.f);
    o0.y = fmaxf(dvd * (a0[1] + a1[1]) + b0.y, 0.f);
    o0.z = fmaxf(dvd * (a0[2] + a1[2]) + b0.z, 0.f);
    o0.w = fmaxf(dvd * (a0[3] + a1[3]) + b0.w, 0.f);
    o1.x = fmaxf(dvd * (a0[4] + a1[4]) + b1.x, 0.f);
    o1.y = fmaxf(dvd * (a0[5] + a1[5]) + b1.y, 0.f);
    o1.z = fmaxf(dvd * (a0[6] + a1[6]) + b1.z, 0.f);
    o1.w = fmaxf(dvd * (a0[7] + a1[7]) + b1.w, 0.f);

    float* outrow = out + (size_t)warp * HID + colOff;
    *reinterpret_cast<float4*>(outrow) = o0;
    *reinterpret_cast<float4*>(outrow + 4) = o1;
}

// ---------------- fused pooling + output head ----------------
__global__ void pool_out_kernel(const float* __restrict__ h, const void* __restrict__ batch,
                                int n, const float* __restrict__ W, const float* __restrict__ b,
                                float* __restrict__ out) {
    __shared__ int sRange[2];
    __shared__ float sPool[HID];
    int g = blockIdx.x;
    int tid = threadIdx.x;
    if (tid < 2) {
        int target = g + tid;
        int is64 = g_is64;
        int lo = 0, hi = n;
        while (lo < hi) {
            int mid = (lo + hi) >> 1;
            if (get_idx(batch, mid, is64) < target) lo = mid + 1; else hi = mid;
        }
        sRange[tid] = lo;
    }
    __syncthreads();
    int beg = sRange[0];
    int end = sRange[1];
    float sum = 0.0f;
    for (int i = beg; i < end; i++) sum += h[(size_t)i * HID + tid];
    sPool[tid] = sum / fmaxf((float)(end - beg), 1.0f);
    __syncthreads();

    {
        int c = tid & 15;
        int k0 = (tid >> 4) * 16;
        float p = 0.0f;
#pragma unroll
        for (int k = 0; k < 16; k++) p += sPool[k0 + k] * W[(k0 + k) * NCLS + c];
        __shared__ float sAll[16][NCLS];
        sAll[tid >> 4][c] = p;
        __syncthreads();
        if (tid < NCLS) {
            float s = b[tid];
#pragma unroll
            for (int q = 0; q < 16; q++) s += sAll[q][tid];
            out[g * NCLS + tid] = s;
        }
    }
}

// ---------------- launch ----------------
extern "C" void kernel_launch(void* const* d_in, const int* in_sizes, int n_in,
                              void* d_out, int out_size) {
    const float* x     = (const float*)d_in[0];
    const void*  ei    = d_in[1];
    const void*  batch = d_in[2];
    const float* W_in  = (const float*)d_in[3];
    const float* b_in  = (const float*)d_in[4];
    const float* W1    = (const float*)d_in[5];
    const float* b1    = (const float*)d_in[6];
    const float* W2    = (const float*)d_in[7];
    const float* b2    = (const float*)d_in[8];
    const float* W_out = (const float*)d_in[9];
    const float* b_out = (const float*)d_in[10];

    const int N = in_sizes[0] / INDIM;
    const int E = in_sizes[1] / 2;

    float *bufA, *dinv, *Wcomb, *bcomb;
    __nv_bfloat16* bufH;
    int *indeg, *row_ptr, *cursor, *csr_src, *localscan;
    cudaGetSymbolAddress((void**)&bufA, g_bufA);
    cudaGetSymbolAddress((void**)&bufH, g_bufH);
    cudaGetSymbolAddress((void**)&Wcomb, g_Wcomb);
    cudaGetSymbolAddress((void**)&bcomb, g_bcomb);
    cudaGetSymbolAddress((void**)&dinv, g_dinv);
    cudaGetSymbolAddress((void**)&indeg, g_indeg);
    cudaGetSymbolAddress((void**)&row_ptr, g_row_ptr);
    cudaGetSymbolAddress((void**)&cursor, g_cursor);
    cudaGetSymbolAddress((void**)&csr_src, g_csr_src);
    cudaGetSymbolAddress((void**)&localscan, g_localscan);

    static cudaStream_t sSide = nullptr;
    static cudaEvent_t evFork = nullptr, evJoin = nullptr;
    if (sSide == nullptr) {
        cudaStreamCreateWithFlags(&sSide, cudaStreamNonBlocking);
        cudaEventCreateWithFlags(&evFork, cudaEventDisableTiming);
        cudaEventCreateWithFlags(&evJoin, cudaEventDisableTiming);
    }

    const int GEMM_GRID = 296;   // 148 SMs x 2 CTAs

    // ---- fork: preprocessing on side stream ----
    cudaEventRecord(evFork, 0);
    cudaStreamWaitEvent(sSide, evFork, 0);

    detect_dtype_kernel<<<1, 256, 0, sSide>>>((const int*)ei, 4096);
    cudaMemsetAsync(indeg, 0, N * sizeof(int), sSide);
    hist_dst_kernel<<<(E + 255) / 256, 256, 0, sSide>>>(ei, E, indeg);
    const int nb = (N + 1023) / 1024;
    scan_local_kernel<<<nb, 1024, 0, sSide>>>(indeg, localscan, N);
    scan_finalize_kernel<<<(N + 255) / 256, 256, 0, sSide>>>(indeg, localscan, row_ptr, cursor, dinv, N);
    fill_csr_kernel<<<(E + 255) / 256, 256, 0, sSide>>>(ei, E, cursor, csr_src);
    cudaEventRecord(evJoin, sSide);

    // ---- main stream ----
    // fold layer-0 linear into layer-1: Wcomb = W_in@W1, bcomb = b_in@W1 (fp32)
    weight_combine_kernel<<<INDIM + 1, HID>>>(W_in, b_in, W1, Wcomb, bcomb);
    // GEMM_a: bufH = bf16(x @ Wcomb + bcomb)   (K=128)
    tf32gemm_kernel<<<GEMM_GRID, 256>>>(x, Wcomb, nullptr, bufH, N, INDIM, bcomb);

    // ---- join: need CSR + dinv ----
    cudaStreamWaitEvent(0, evJoin, 0);

    gather_kernel<<<(N * 32 + 255) / 256, 256>>>(bufH, bufA, row_ptr, csr_src, dinv, b1, N);

    tf32gemm_kernel<<<GEMM_GRID, 256>>>(bufA, W2, nullptr, bufH, N, HID, nullptr);
    gather_kernel<<<(N * 32 + 255) / 256, 256>>>(bufH, bufA, row_ptr, csr_src, dinv, b2, N);

    pool_out_kernel<<<NGRAPH, HID>>>(bufA, batch, N, W_out, b_out, (float*)d_out);
}